// round 1
// baseline (speedup 1.0000x reference)
#include <cuda_runtime.h>
#include <math.h>

#define BB 2
#define SS 2048
#define HH 16
#define NOPE 128
#define ROPE 64
#define VD 128
#define DQK 192           // NOPE + ROPE
#define QR 1536
#define KVR 512
#define NQ (HH*DQK)       // 3072
#define NKV (HH*(NOPE+VD))// 4096
#define MM (BB*SS)        // 4096
#define SCALE 0.07216878364870323f  // 1/sqrt(192)

// Scratch (device globals: allocation-free rule)
__device__ float g_q[(size_t)BB*HH*SS*DQK];   // [b,h,s,192]  q_nope | q_pe(roped)
__device__ float g_k[(size_t)BB*HH*SS*DQK];   // [b,h,s,192]  k_nope | k_pe(roped, replicated per head)
__device__ float g_v[(size_t)BB*HH*SS*VD];    // [b,h,s,128]

// ---------------------------------------------------------------------------
// NT SGEMM: C[m,n] = sum_k A[m,k] * W[n,k]; 64x64 tile, BK=16, 256 thr, 4x4 micro
// MODE 0: q up-projection epilogue -> g_q ; MODE 1: kv -> g_k/g_v
// ---------------------------------------------------------------------------
template<int MODE>
__global__ __launch_bounds__(256) void gemm_nt_kernel(const float* __restrict__ A,
                                                      const float* __restrict__ W,
                                                      int K) {
    __shared__ float As[16][68];
    __shared__ float Ws[16][68];
    const int bm = blockIdx.y * 64, bn = blockIdx.x * 64;
    const int tid = threadIdx.x;
    const int tx = tid & 15, ty = tid >> 4;
    const int lr = tid >> 2, lk = (tid & 3) << 2;

    float acc[4][4] = {};
    const float* Ap = A + (size_t)(bm + lr) * K + lk;
    const float* Wp = W + (size_t)(bn + lr) * K + lk;

    for (int k0 = 0; k0 < K; k0 += 16) {
        float4 a = *(const float4*)(Ap + k0);
        float4 w = *(const float4*)(Wp + k0);
        As[lk + 0][lr] = a.x; As[lk + 1][lr] = a.y; As[lk + 2][lr] = a.z; As[lk + 3][lr] = a.w;
        Ws[lk + 0][lr] = w.x; Ws[lk + 1][lr] = w.y; Ws[lk + 2][lr] = w.z; Ws[lk + 3][lr] = w.w;
        __syncthreads();
#pragma unroll
        for (int kk = 0; kk < 16; kk++) {
            float4 av = *(const float4*)&As[kk][ty << 2];
            float4 wv = *(const float4*)&Ws[kk][tx << 2];
            float ar[4] = {av.x, av.y, av.z, av.w};
            float wr[4] = {wv.x, wv.y, wv.z, wv.w};
#pragma unroll
            for (int i = 0; i < 4; i++)
#pragma unroll
                for (int j = 0; j < 4; j++) acc[i][j] += ar[i] * wr[j];
        }
        __syncthreads();
    }

#pragma unroll
    for (int i = 0; i < 4; i++) {
        int m = bm + (ty << 2) + i;
        int b = m / SS, s = m % SS;
#pragma unroll
        for (int j = 0; j < 4; j++) {
            int n = bn + (tx << 2) + j;
            if (MODE == 0) {
                int h = n / DQK, d = n % DQK;
                g_q[(((size_t)(b * HH + h)) * SS + s) * DQK + d] = acc[i][j];
            } else {
                int h = n >> 8, d = n & 255;
                if (d < NOPE)
                    g_k[(((size_t)(b * HH + h)) * SS + s) * DQK + d] = acc[i][j];
                else
                    g_v[(((size_t)(b * HH + h)) * SS + s) * VD + (d - NOPE)] = acc[i][j];
            }
        }
    }
}

// ---------------------------------------------------------------------------
// RoPE: rope q_pe in-place; rope PE -> k_pe replicated into g_k[..., 128:192]
// one thread per (b, s, i<32); note cos[i+32] == cos[i], sin[i+32] == sin[i]
// ---------------------------------------------------------------------------
__global__ void rope_kernel(const float* __restrict__ PE,
                            const float* __restrict__ cosb,
                            const float* __restrict__ sinb) {
    int t = blockIdx.x * blockDim.x + threadIdx.x;
    if (t >= BB * SS * 32) return;
    int i = t & 31;
    int bs = t >> 5;
    int b = bs / SS, s = bs % SS;

    float c  = cosb[(size_t)bs * ROPE + i];
    float sn = sinb[(size_t)bs * ROPE + i];

    float p1 = PE[(size_t)bs * ROPE + i];
    float p2 = PE[(size_t)bs * ROPE + i + 32];
    float k1 = p1 * c - p2 * sn;
    float k2 = p2 * c + p1 * sn;

#pragma unroll
    for (int h = 0; h < HH; h++) {
        size_t base = (((size_t)(b * HH + h)) * SS + s) * DQK;
        float x1 = g_q[base + NOPE + i];
        float x2 = g_q[base + NOPE + i + 32];
        g_q[base + NOPE + i]      = x1 * c - x2 * sn;
        g_q[base + NOPE + i + 32] = x2 * c + x1 * sn;
        g_k[base + NOPE + i]      = k1;
        g_k[base + NOPE + i + 32] = k2;
    }
}

// ---------------------------------------------------------------------------
// Flash attention (causal): BQ=64, BK=64, 256 threads, fp32 SIMT
// grid = (S/64, H, B)
// ---------------------------------------------------------------------------
#define BQ 64
#define BKT 64
#define SMEM_FLOATS (DQK*BQ + DQK*BKT + BKT*VD + BQ*65 + 3*BQ)

extern __shared__ float fsmem[];

__global__ __launch_bounds__(256) void flash_kernel(float* __restrict__ out) {
    const int qt = blockIdx.x, h = blockIdx.y, b = blockIdx.z;
    const int tid = threadIdx.x;
    const int tx = tid & 15, ty = tid >> 4;

    float* sQ = fsmem;                 // [192][64] transposed
    float* sK = sQ + DQK * BQ;         // [192][64] transposed
    float* sV = sK + DQK * BKT;        // [64][128]
    float* sS = sV + BKT * VD;         // [64][65]
    float* sM = sS + BQ * 65;
    float* sL = sM + BQ;
    float* sA = sL + BQ;

    const int q0 = qt * BQ;
    const size_t bh = (size_t)(b * HH + h);
    const size_t qbase = (bh * SS + q0) * DQK;

    // load Q tile transposed
    for (int idx = tid; idx < BQ * 48; idx += 256) {
        int r = idx / 48, d4 = (idx % 48) << 2;
        float4 v = *(const float4*)&g_q[qbase + (size_t)r * DQK + d4];
        sQ[(d4 + 0) * BQ + r] = v.x; sQ[(d4 + 1) * BQ + r] = v.y;
        sQ[(d4 + 2) * BQ + r] = v.z; sQ[(d4 + 3) * BQ + r] = v.w;
    }
    if (tid < BQ) { sM[tid] = -1e30f; sL[tid] = 0.f; }

    float acc[4][8] = {};

    for (int kt = 0; kt <= qt; kt++) {
        const int k0 = kt * BKT;
        const size_t kbase = (bh * SS + k0) * DQK;
        const size_t vbase = (bh * SS + k0) * VD;

        __syncthreads();  // previous iter's sK/sV/sS consumers done (also covers Q/init on iter 0)

        for (int idx = tid; idx < BKT * 48; idx += 256) {
            int r = idx / 48, d4 = (idx % 48) << 2;
            float4 v = *(const float4*)&g_k[kbase + (size_t)r * DQK + d4];
            sK[(d4 + 0) * BKT + r] = v.x; sK[(d4 + 1) * BKT + r] = v.y;
            sK[(d4 + 2) * BKT + r] = v.z; sK[(d4 + 3) * BKT + r] = v.w;
        }
        for (int idx = tid; idx < BKT * 32; idx += 256) {
            int r = idx / 32, d4 = (idx % 32) << 2;
            *(float4*)&sV[r * VD + d4] = *(const float4*)&g_v[vbase + (size_t)r * VD + d4];
        }
        __syncthreads();

        // ---- scores: 4x4 per thread over d=0..191 ----
        float sc[4][4] = {};
#pragma unroll 4
        for (int d = 0; d < DQK; d++) {
            float4 qv = *(const float4*)&sQ[d * BQ + (ty << 2)];
            float4 kv = *(const float4*)&sK[d * BKT + (tx << 2)];
            float qr[4] = {qv.x, qv.y, qv.z, qv.w};
            float kr[4] = {kv.x, kv.y, kv.z, kv.w};
#pragma unroll
            for (int i = 0; i < 4; i++)
#pragma unroll
                for (int j = 0; j < 4; j++) sc[i][j] += qr[i] * kr[j];
        }
#pragma unroll
        for (int i = 0; i < 4; i++) {
            int qi = q0 + (ty << 2) + i;
#pragma unroll
            for (int j = 0; j < 4; j++) {
                int kj = k0 + (tx << 2) + j;
                float v = sc[i][j] * SCALE;
                if (kj > qi) v = -1e30f;
                sS[((ty << 2) + i) * 65 + (tx << 2) + j] = v;
            }
        }
        __syncthreads();

        // ---- online softmax row pass ----
        if (tid < BQ) {
            float* row = &sS[tid * 65];
            float mo = sM[tid];
            float mx = mo;
            for (int j = 0; j < BKT; j++) mx = fmaxf(mx, row[j]);
            float alpha = expf(mo - mx);
            float sum = 0.f;
            for (int j = 0; j < BKT; j++) {
                float p = expf(row[j] - mx);
                row[j] = p;
                sum += p;
            }
            sL[tid] = alpha * sL[tid] + sum;
            sM[tid] = mx;
            sA[tid] = alpha;
        }
        __syncthreads();

        // ---- PV: acc = alpha*acc + P @ V ; 4 rows x 8 cols per thread ----
#pragma unroll
        for (int i = 0; i < 4; i++) {
            float a = sA[(ty << 2) + i];
#pragma unroll
            for (int j = 0; j < 8; j++) acc[i][j] *= a;
        }
        for (int k = 0; k < BKT; k++) {
            float p0 = sS[((ty << 2) + 0) * 65 + k];
            float p1 = sS[((ty << 2) + 1) * 65 + k];
            float p2 = sS[((ty << 2) + 2) * 65 + k];
            float p3 = sS[((ty << 2) + 3) * 65 + k];
            float4 v0 = *(const float4*)&sV[k * VD + (tx << 3)];
            float4 v1 = *(const float4*)&sV[k * VD + (tx << 3) + 4];
            float vr[8] = {v0.x, v0.y, v0.z, v0.w, v1.x, v1.y, v1.z, v1.w};
#pragma unroll
            for (int j = 0; j < 8; j++) {
                acc[0][j] += p0 * vr[j];
                acc[1][j] += p1 * vr[j];
                acc[2][j] += p2 * vr[j];
                acc[3][j] += p3 * vr[j];
            }
        }
    }

    // epilogue: out[b, q, h, d]
#pragma unroll
    for (int i = 0; i < 4; i++) {
        int r = (ty << 2) + i;
        float inv = 1.f / sL[r];
        size_t ob = (((size_t)b * SS + q0 + r) * HH + h) * VD + (tx << 3);
#pragma unroll
        for (int j = 0; j < 8; j++) out[ob + j] = acc[i][j] * inv;
    }
}

// ---------------------------------------------------------------------------
extern "C" void kernel_launch(void* const* d_in, const int* in_sizes, int n_in,
                              void* d_out, int out_size) {
    const float* Q    = (const float*)d_in[0];
    const float* KV   = (const float*)d_in[1];
    const float* PE   = (const float*)d_in[2];
    const float* WUQ  = (const float*)d_in[3];
    const float* WUKV = (const float*)d_in[4];
    const float* cosb = (const float*)d_in[5];
    const float* sinb = (const float*)d_in[6];
    // d_in[7] = mask: exact causal (exp(-10000) underflows to 0 in fp32) -> unused
    float* out = (float*)d_out;

    static int smem_set = 0;
    size_t flash_smem = (size_t)SMEM_FLOATS * sizeof(float);
    cudaFuncSetAttribute(flash_kernel, cudaFuncAttributeMaxDynamicSharedMemorySize,
                         (int)flash_smem);
    (void)smem_set; (void)in_sizes; (void)n_in; (void)out_size;

    dim3 g1(NQ / 64, MM / 64);    // (48, 64)
    gemm_nt_kernel<0><<<g1, 256>>>(Q, WUQ, QR);

    dim3 g2(NKV / 64, MM / 64);   // (64, 64)
    gemm_nt_kernel<1><<<g2, 256>>>(KV, WUKV, KVR);

    int nrope = BB * SS * 32;
    rope_kernel<<<(nrope + 255) / 256, 256>>>(PE, cosb, sinb);

    dim3 gf(SS / BQ, HH, BB);     // (32, 16, 2)
    flash_kernel<<<gf, 256, flash_smem>>>(out);
}

// round 3
// speedup vs baseline: 3.1024x; 3.1024x over previous
#include <cuda_runtime.h>
#include <math.h>
#include <stdint.h>

#define BB 2
#define SS 2048
#define HH 16
#define NOPE 128
#define ROPE 64
#define VD 128
#define DQK 192           // NOPE + ROPE
#define QR 1536
#define KVR 512
#define NQ (HH*DQK)       // 3072
#define NKV (HH*(NOPE+VD))// 4096
#define MM (BB*SS)        // 4096
#define SCALE 0.07216878364870323f  // 1/sqrt(192)

// Scratch (device globals: allocation-free rule)
__device__ float g_q[(size_t)BB*HH*SS*DQK];   // [b,h,s,192]
__device__ float g_k[(size_t)BB*HH*SS*DQK];   // [b,h,s,192]
__device__ float g_v[(size_t)BB*HH*SS*VD];    // [b,h,s,128]

// ---------------------------------------------------------------------------
// mma.sync tf32 helpers (sm_80+ path -> HMMA tensor pipe, no 'a' target needed)
// ---------------------------------------------------------------------------
__device__ __forceinline__ void mma8(float* c, const uint32_t* a, const uint32_t* b) {
    asm volatile(
        "mma.sync.aligned.m16n8k8.row.col.f32.tf32.tf32.f32 "
        "{%0,%1,%2,%3}, {%4,%5,%6,%7}, {%8,%9}, {%0,%1,%2,%3};"
        : "+f"(c[0]), "+f"(c[1]), "+f"(c[2]), "+f"(c[3])
        : "r"(a[0]), "r"(a[1]), "r"(a[2]), "r"(a[3]), "r"(b[0]), "r"(b[1]));
}
// 3xTF32 split: hi = rna_tf32(x); lo = x - hi (raw residual; HW truncation ~2^-22)
__device__ __forceinline__ void split3(float x, uint32_t& hi, uint32_t& lo) {
    float h;
    asm("cvt.rna.tf32.f32 %0, %1;" : "=f"(h) : "f"(x));
    hi = __float_as_uint(h);
    lo = __float_as_uint(x - h);
}

// ---------------------------------------------------------------------------
// GEMM (3xTF32): C[m,n] = sum_k A[m,k]*W[n,k]; CTA 128x128, warp 32x64, Kc=32
// MODE 0 -> g_q ; MODE 1 -> g_k/g_v
// ---------------------------------------------------------------------------
#define GP 44   // smem row pad (floats): conflict-free frags + 16B aligned

template<int MODE>
__global__ __launch_bounds__(256) void gemm_mma_kernel(const float* __restrict__ A,
                                                       const float* __restrict__ W,
                                                       int K) {
    __shared__ float As[128 * GP];
    __shared__ float Ws[128 * GP];
    const int tid = threadIdx.x;
    const int w = tid >> 5, lane = tid & 31;
    const int g = lane >> 2, t = lane & 3;
    const int bm = blockIdx.y * 128, bn = blockIdx.x * 128;
    const int mw = (w >> 1) * 32;   // 0,32,64,96
    const int nw = (w & 1) * 64;    // 0,64

    float c[2][8][4] = {};

    for (int k0 = 0; k0 < K; k0 += 32) {
#pragma unroll
        for (int i = 0; i < 4; i++) {
            int idx = tid + i * 256;
            int r = idx >> 3, f = (idx & 7) << 2;
            *(float4*)&As[r * GP + f] = *(const float4*)&A[(size_t)(bm + r) * K + k0 + f];
            *(float4*)&Ws[r * GP + f] = *(const float4*)&W[(size_t)(bn + r) * K + k0 + f];
        }
        __syncthreads();

#pragma unroll
        for (int kk = 0; kk < 4; kk++) {
            const int kb = kk << 3;
            uint32_t ah[2][4], al[2][4];
#pragma unroll
            for (int mf = 0; mf < 2; mf++) {
                const float* p = &As[(mw + mf * 16 + g) * GP + kb + t];
                split3(p[0],        ah[mf][0], al[mf][0]);
                split3(p[8 * GP],   ah[mf][1], al[mf][1]);
                split3(p[4],        ah[mf][2], al[mf][2]);
                split3(p[8 * GP + 4], ah[mf][3], al[mf][3]);
            }
#pragma unroll
            for (int nf = 0; nf < 8; nf++) {
                const float* p = &Ws[(nw + nf * 8 + g) * GP + kb + t];
                uint32_t bh[2], bl[2];
                split3(p[0], bh[0], bl[0]);
                split3(p[4], bh[1], bl[1]);
#pragma unroll
                for (int mf = 0; mf < 2; mf++) {
                    mma8(c[mf][nf], ah[mf], bh);
                    mma8(c[mf][nf], ah[mf], bl);
                    mma8(c[mf][nf], al[mf], bh);
                }
            }
        }
        __syncthreads();
    }

    // epilogue scatter
#pragma unroll
    for (int mf = 0; mf < 2; mf++) {
#pragma unroll
        for (int i = 0; i < 4; i++) {
            const int m = bm + mw + mf * 16 + g + ((i >> 1) << 3);
            const int b = m >> 11, s = m & 2047;
#pragma unroll
            for (int nf = 0; nf < 8; nf++) {
                const int n = bn + nw + nf * 8 + (t << 1) + (i & 1);
                const float v = c[mf][nf][i];
                if (MODE == 0) {
                    const int h = n / DQK, d = n % DQK;
                    g_q[(((size_t)(b * HH + h)) * SS + s) * DQK + d] = v;
                } else {
                    const int h = n >> 8, d = n & 255;
                    if (d < NOPE)
                        g_k[(((size_t)(b * HH + h)) * SS + s) * DQK + d] = v;
                    else
                        g_v[(((size_t)(b * HH + h)) * SS + s) * VD + (d - NOPE)] = v;
                }
            }
        }
    }
}

// ---------------------------------------------------------------------------
// RoPE: rope q_pe in-place; rope PE -> k_pe replicated into g_k[..., 128:192]
// ---------------------------------------------------------------------------
__global__ void rope_kernel(const float* __restrict__ PE,
                            const float* __restrict__ cosb,
                            const float* __restrict__ sinb) {
    int tt = blockIdx.x * blockDim.x + threadIdx.x;
    if (tt >= BB * SS * 32) return;
    int i = tt & 31;
    int bs = tt >> 5;
    int b = bs / SS, s = bs % SS;

    float c  = cosb[(size_t)bs * ROPE + i];
    float sn = sinb[(size_t)bs * ROPE + i];

    float p1 = PE[(size_t)bs * ROPE + i];
    float p2 = PE[(size_t)bs * ROPE + i + 32];
    float k1 = p1 * c - p2 * sn;
    float k2 = p2 * c + p1 * sn;

#pragma unroll
    for (int h = 0; h < HH; h++) {
        size_t base = (((size_t)(b * HH + h)) * SS + s) * DQK;
        float x1 = g_q[base + NOPE + i];
        float x2 = g_q[base + NOPE + i + 32];
        g_q[base + NOPE + i]      = x1 * c - x2 * sn;
        g_q[base + NOPE + i + 32] = x2 * c + x1 * sn;
        g_k[base + NOPE + i]      = k1;
        g_k[base + NOPE + i + 32] = k2;
    }
}

// ---------------------------------------------------------------------------
// Flash attention (causal), 3xTF32 mma: BQ=BK=64, 256 threads
// scores: 8 warps = 2m x 2n x 2(k-split of 96);  PV: 8 warps = 2m x 4n
// ---------------------------------------------------------------------------
#define QP 196   // Q/K smem row pad (floats)
#define VP 136   // V pad
#define SP 68    // S pad
#define FL_SMEM_FLOATS (64*QP*2 + 64*VP + 64*SP*2 + 3*64)

extern __shared__ float fsm[];

__global__ __launch_bounds__(256) void flash_kernel(float* __restrict__ out) {
    const int qt = blockIdx.x, h = blockIdx.y, b = blockIdx.z;
    const int tid = threadIdx.x;
    const int w = tid >> 5, lane = tid & 31;
    const int g = lane >> 2, t = lane & 3;

    float* sQ  = fsm;
    float* sK  = sQ + 64 * QP;
    float* sV  = sK + 64 * QP;
    float* sS0 = sV + 64 * VP;
    float* sS1 = sS0 + 64 * SP;
    float* sM  = sS1 + 64 * SP;
    float* sL  = sM + 64;
    float* sA  = sL + 64;

    // score warp mapping
    const int khalf = (w & 1) * 96;
    const int smw = ((w >> 1) & 1) * 32;
    const int snw = (w >> 2) * 32;
    float* sSp = (w & 1) ? sS1 : sS0;
    // PV warp mapping
    const int pmw = (w & 1) * 32;
    const int pnw = (w >> 1) * 32;

    const int q0 = qt * 64;
    const size_t bh = (size_t)(b * HH + h);
    const size_t qbase = (bh * SS + q0) * DQK;

    // load Q tile [64][192] row-major
#pragma unroll
    for (int i = 0; i < 12; i++) {
        int idx = tid + i * 256;
        int r = idx / 48, f = (idx % 48) << 2;
        *(float4*)&sQ[r * QP + f] = *(const float4*)&g_q[qbase + (size_t)r * DQK + f];
    }
    if (tid < 64) { sM[tid] = -1e30f; sL[tid] = 0.f; }

    float po[2][4][4] = {};

    for (int kt = 0; kt <= qt; kt++) {
        const int k0 = kt * 64;
        const size_t kbase = (bh * SS + k0) * DQK;
        const size_t vbase = (bh * SS + k0) * VD;

        __syncthreads();  // protect sK/sV/sS0 from previous iteration's readers
#pragma unroll
        for (int i = 0; i < 12; i++) {
            int idx = tid + i * 256;
            int r = idx / 48, f = (idx % 48) << 2;
            *(float4*)&sK[r * QP + f] = *(const float4*)&g_k[kbase + (size_t)r * DQK + f];
        }
#pragma unroll
        for (int i = 0; i < 8; i++) {
            int idx = tid + i * 256;
            int r = idx >> 5, f = (idx & 31) << 2;
            *(float4*)&sV[r * VP + f] = *(const float4*)&g_v[vbase + (size_t)r * VD + f];
        }
        __syncthreads();

        // ---- scores (partial over k-half) ----
        float sc[2][4][4] = {};
#pragma unroll
        for (int kk = 0; kk < 12; kk++) {
            const int kb = khalf + (kk << 3);
            uint32_t ah[2][4], al[2][4];
#pragma unroll
            for (int mf = 0; mf < 2; mf++) {
                const float* p = &sQ[(smw + mf * 16 + g) * QP + kb + t];
                split3(p[0],          ah[mf][0], al[mf][0]);
                split3(p[8 * QP],     ah[mf][1], al[mf][1]);
                split3(p[4],          ah[mf][2], al[mf][2]);
                split3(p[8 * QP + 4], ah[mf][3], al[mf][3]);
            }
#pragma unroll
            for (int nf = 0; nf < 4; nf++) {
                const float* p = &sK[(snw + nf * 8 + g) * QP + kb + t];
                uint32_t bhf[2], blf[2];
                split3(p[0], bhf[0], blf[0]);
                split3(p[4], bhf[1], blf[1]);
#pragma unroll
                for (int mf = 0; mf < 2; mf++) {
                    mma8(sc[mf][nf], ah[mf], bhf);
                    mma8(sc[mf][nf], ah[mf], blf);
                    mma8(sc[mf][nf], al[mf], bhf);
                }
            }
        }
        // write partial scores
#pragma unroll
        for (int mf = 0; mf < 2; mf++) {
            const int r = smw + mf * 16 + g;
#pragma unroll
            for (int nf = 0; nf < 4; nf++) {
                const int cl = snw + nf * 8 + (t << 1);
                *(float2*)&sSp[r * SP + cl]       = make_float2(sc[mf][nf][0], sc[mf][nf][1]);
                *(float2*)&sSp[(r + 8) * SP + cl] = make_float2(sc[mf][nf][2], sc[mf][nf][3]);
            }
        }
        __syncthreads();

        // ---- online softmax row pass ----
        if (tid < 64) {
            const int qi = q0 + tid;
            float* r0 = &sS0[tid * SP];
            float* r1 = &sS1[tid * SP];
            float mo = sM[tid];
            float mx = mo;
            float v[64];
#pragma unroll 8
            for (int j = 0; j < 64; j++) {
                float s = (r0[j] + r1[j]) * SCALE;
                if (k0 + j > qi) s = -1e30f;
                v[j] = s;
                mx = fmaxf(mx, s);
            }
            float alpha = expf(mo - mx);
            float sum = 0.f;
#pragma unroll 8
            for (int j = 0; j < 64; j++) {
                float p = expf(v[j] - mx);
                r0[j] = p;
                sum += p;
            }
            sL[tid] = alpha * sL[tid] + sum;
            sM[tid] = mx;
            sA[tid] = alpha;
        }
        __syncthreads();

        // ---- PV: po = alpha*po + P @ V ----
#pragma unroll
        for (int mf = 0; mf < 2; mf++) {
            const float aa = sA[pmw + mf * 16 + g];
            const float ab = sA[pmw + mf * 16 + g + 8];
#pragma unroll
            for (int nf = 0; nf < 4; nf++) {
                po[mf][nf][0] *= aa; po[mf][nf][1] *= aa;
                po[mf][nf][2] *= ab; po[mf][nf][3] *= ab;
            }
        }
#pragma unroll
        for (int kk = 0; kk < 8; kk++) {
            const int kb = kk << 3;
            uint32_t ah[2][4], al[2][4];
#pragma unroll
            for (int mf = 0; mf < 2; mf++) {
                const float* p = &sS0[(pmw + mf * 16 + g) * SP + kb + t];
                split3(p[0],          ah[mf][0], al[mf][0]);
                split3(p[8 * SP],     ah[mf][1], al[mf][1]);
                split3(p[4],          ah[mf][2], al[mf][2]);
                split3(p[8 * SP + 4], ah[mf][3], al[mf][3]);
            }
#pragma unroll
            for (int nf = 0; nf < 4; nf++) {
                const float* p = &sV[(kb + t) * VP + pnw + nf * 8 + g];
                uint32_t bhf[2], blf[2];
                split3(p[0],      bhf[0], blf[0]);
                split3(p[4 * VP], bhf[1], blf[1]);
#pragma unroll
                for (int mf = 0; mf < 2; mf++) {
                    mma8(po[mf][nf], ah[mf], bhf);
                    mma8(po[mf][nf], ah[mf], blf);
                    mma8(po[mf][nf], al[mf], bhf);
                }
            }
        }
    }

    // epilogue: out[b, q, h, d]
#pragma unroll
    for (int mf = 0; mf < 2; mf++) {
        const int r = pmw + mf * 16 + g;
        const float iv0 = 1.f / sL[r];
        const float iv1 = 1.f / sL[r + 8];
        const size_t ob0 = (((size_t)b * SS + q0 + r) * HH + h) * VD;
        const size_t ob1 = (((size_t)b * SS + q0 + r + 8) * HH + h) * VD;
#pragma unroll
        for (int nf = 0; nf < 4; nf++) {
            const int cl = pnw + nf * 8 + (t << 1);
            *(float2*)&out[ob0 + cl] = make_float2(po[mf][nf][0] * iv0, po[mf][nf][1] * iv0);
            *(float2*)&out[ob1 + cl] = make_float2(po[mf][nf][2] * iv1, po[mf][nf][3] * iv1);
        }
    }
}

// ---------------------------------------------------------------------------
extern "C" void kernel_launch(void* const* d_in, const int* in_sizes, int n_in,
                              void* d_out, int out_size) {
    const float* Q    = (const float*)d_in[0];
    const float* KV   = (const float*)d_in[1];
    const float* PE   = (const float*)d_in[2];
    const float* WUQ  = (const float*)d_in[3];
    const float* WUKV = (const float*)d_in[4];
    const float* cosb = (const float*)d_in[5];
    const float* sinb = (const float*)d_in[6];
    float* out = (float*)d_out;
    (void)in_sizes; (void)n_in; (void)out_size;

    size_t flash_smem = (size_t)FL_SMEM_FLOATS * sizeof(float);
    cudaFuncSetAttribute(flash_kernel, cudaFuncAttributeMaxDynamicSharedMemorySize,
                         (int)flash_smem);

    dim3 g1(NQ / 128, MM / 128);   // (24, 32)
    gemm_mma_kernel<0><<<g1, 256>>>(Q, WUQ, QR);

    dim3 g2(NKV / 128, MM / 128);  // (32, 32)
    gemm_mma_kernel<1><<<g2, 256>>>(KV, WUKV, KVR);

    int nrope = BB * SS * 32;
    rope_kernel<<<(nrope + 255) / 256, 256>>>(PE, cosb, sinb);

    dim3 gf(SS / 64, HH, BB);      // (32, 16, 2)
    flash_kernel<<<gf, 256, flash_smem>>>(out);
}

// round 4
// speedup vs baseline: 4.9340x; 1.5904x over previous
#include <cuda_runtime.h>
#include <cuda_bf16.h>
#include <math.h>
#include <stdint.h>

#define BB 2
#define SS 2048
#define HH 16
#define NOPE 128
#define ROPE 64
#define VD 128
#define DQK 192           // NOPE + ROPE
#define QR 1536
#define KVR 512
#define NQ (HH*DQK)       // 3072
#define NKV (HH*(NOPE+VD))// 4096
#define MM (BB*SS)        // 4096
#define SCALE 0.07216878364870323f  // 1/sqrt(192)

// Packed split-bf16 scratch: each uint32 = (hi_bf16 | lo_bf16<<16), x = hi + lo
__device__ uint32_t g_q2[(size_t)BB*HH*SS*DQK];   // [b,h,s,192]
__device__ uint32_t g_k2[(size_t)BB*HH*SS*DQK];   // [b,h,s,192]
__device__ uint32_t g_v2t[(size_t)BB*HH*VD*SS];   // [b,h,d,s]  (transposed!)

// ---------------------------------------------------------------------------
// helpers
// ---------------------------------------------------------------------------
__device__ __forceinline__ uint32_t smem_u32(const void* p) {
    uint32_t a;
    asm("{ .reg .u64 t; cvta.to.shared.u64 t, %1; cvt.u32.u64 %0, t; }" : "=r"(a) : "l"(p));
    return a;
}
__device__ __forceinline__ void ldsm4(uint32_t* r, uint32_t addr) {
    asm volatile("ldmatrix.sync.aligned.m8n8.x4.shared.b16 {%0,%1,%2,%3}, [%4];"
                 : "=r"(r[0]), "=r"(r[1]), "=r"(r[2]), "=r"(r[3]) : "r"(addr));
}
__device__ __forceinline__ void mma16(float* c, const uint32_t* a, const uint32_t* b) {
    asm volatile("mma.sync.aligned.m16n8k16.row.col.f32.bf16.bf16.f32 "
                 "{%0,%1,%2,%3}, {%4,%5,%6,%7}, {%8,%9}, {%0,%1,%2,%3};"
                 : "+f"(c[0]), "+f"(c[1]), "+f"(c[2]), "+f"(c[3])
                 : "r"(a[0]), "r"(a[1]), "r"(a[2]), "r"(a[3]), "r"(b[0]), "r"(b[1]));
}
__device__ __forceinline__ uint32_t bpack(float x) {
    __nv_bfloat16 h = __float2bfloat16_rn(x);
    float r = x - __bfloat162float(h);
    __nv_bfloat16 l = __float2bfloat16_rn(r);
    return (uint32_t)__bfloat16_as_ushort(h) | ((uint32_t)__bfloat16_as_ushort(l) << 16);
}
__device__ __forceinline__ float bunpack(uint32_t u) {
    return __bfloat162float(__ushort_as_bfloat16((unsigned short)(u & 0xffffu)))
         + __bfloat162float(__ushort_as_bfloat16((unsigned short)(u >> 16)));
}
// unpack 2 packed uints -> (hi0|hi1) and (lo0|lo1)
#define PERM_HI 0x5410
#define PERM_LO 0x7632

// ---------------------------------------------------------------------------
// GEMM (split-bf16, 3-term): C[m,n] = sum_k A[m,k]*W[n,k]
// CTA 128x128, warp 32x64, K-chunk 32.  MODE 0 -> g_q2 ; MODE 1 -> g_k2/g_v2t
// ---------------------------------------------------------------------------
#define GP 40   // smem row pitch (halfs)

__device__ __forceinline__ void split_store4(unsigned short* H, unsigned short* L,
                                             int off, float4 v) {
    __nv_bfloat16 h0 = __float2bfloat16_rn(v.x), h1 = __float2bfloat16_rn(v.y);
    __nv_bfloat16 h2 = __float2bfloat16_rn(v.z), h3 = __float2bfloat16_rn(v.w);
    ushort4 hh;
    hh.x = __bfloat16_as_ushort(h0); hh.y = __bfloat16_as_ushort(h1);
    hh.z = __bfloat16_as_ushort(h2); hh.w = __bfloat16_as_ushort(h3);
    *(ushort4*)(H + off) = hh;
    ushort4 ll;
    ll.x = __bfloat16_as_ushort(__float2bfloat16_rn(v.x - __bfloat162float(h0)));
    ll.y = __bfloat16_as_ushort(__float2bfloat16_rn(v.y - __bfloat162float(h1)));
    ll.z = __bfloat16_as_ushort(__float2bfloat16_rn(v.z - __bfloat162float(h2)));
    ll.w = __bfloat16_as_ushort(__float2bfloat16_rn(v.w - __bfloat162float(h3)));
    *(ushort4*)(L + off) = ll;
}

template<int MODE>
__global__ __launch_bounds__(256) void gemm_mma_kernel(const float* __restrict__ A,
                                                       const float* __restrict__ W,
                                                       int K) {
    __shared__ unsigned short Ah[128 * GP], Al[128 * GP], Wh[128 * GP], Wl[128 * GP];
    const int tid = threadIdx.x;
    const int w = tid >> 5, lane = tid & 31;
    const int g = lane >> 2, t = lane & 3;
    const int lrow = lane & 15, lc8 = (lane >> 4) << 3;
    const int bm = blockIdx.y * 128, bn = blockIdx.x * 128;
    const int mw = (w >> 1) * 32, nw = (w & 1) * 64;
    const uint32_t uAh = smem_u32(Ah), uAl = smem_u32(Al);
    const uint32_t uWh = smem_u32(Wh), uWl = smem_u32(Wl);

    float c[2][8][4] = {};

    for (int k0 = 0; k0 < K; k0 += 32) {
#pragma unroll
        for (int i = 0; i < 4; i++) {
            int idx = tid + i * 256;
            int r = idx >> 3, f = (idx & 7) << 2;
            float4 a = *(const float4*)&A[(size_t)(bm + r) * K + k0 + f];
            float4 b = *(const float4*)&W[(size_t)(bn + r) * K + k0 + f];
            split_store4(Ah, Al, r * GP + f, a);
            split_store4(Wh, Wl, r * GP + f, b);
        }
        __syncthreads();

#pragma unroll
        for (int kk = 0; kk < 2; kk++) {
            const int kb = kk << 4;
            uint32_t ah[2][4], al[2][4];
#pragma unroll
            for (int mf = 0; mf < 2; mf++) {
                uint32_t off = (uint32_t)(((mw + mf * 16 + lrow) * GP + kb + lc8) * 2);
                ldsm4(ah[mf], uAh + off);
                ldsm4(al[mf], uAl + off);
            }
#pragma unroll
            for (int p = 0; p < 4; p++) {
                uint32_t off = (uint32_t)(((nw + p * 16 + lrow) * GP + kb + lc8) * 2);
                uint32_t b4h[4], b4l[4];
                ldsm4(b4h, uWh + off);
                ldsm4(b4l, uWl + off);
                uint32_t bhe[2] = {b4h[0], b4h[2]}, bho[2] = {b4h[1], b4h[3]};
                uint32_t ble[2] = {b4l[0], b4l[2]}, blq[2] = {b4l[1], b4l[3]};
#pragma unroll
                for (int mf = 0; mf < 2; mf++) {
                    mma16(c[mf][2 * p],     ah[mf], bhe);
                    mma16(c[mf][2 * p],     ah[mf], ble);
                    mma16(c[mf][2 * p],     al[mf], bhe);
                    mma16(c[mf][2 * p + 1], ah[mf], bho);
                    mma16(c[mf][2 * p + 1], ah[mf], blq);
                    mma16(c[mf][2 * p + 1], al[mf], bho);
                }
            }
        }
        __syncthreads();
    }

    // epilogue: pack split-bf16 and scatter
#pragma unroll
    for (int mf = 0; mf < 2; mf++) {
#pragma unroll
        for (int i = 0; i < 4; i++) {
            const int m = bm + mw + mf * 16 + g + ((i >> 1) << 3);
            const int b = m >> 11, s = m & 2047;
#pragma unroll
            for (int nf = 0; nf < 8; nf++) {
                const int n = bn + nw + nf * 8 + (t << 1) + (i & 1);
                const uint32_t pv = bpack(c[mf][nf][i]);
                if (MODE == 0) {
                    const int h = n / DQK, d = n % DQK;
                    g_q2[(((size_t)(b * HH + h)) * SS + s) * DQK + d] = pv;
                } else {
                    const int h = n >> 8, d = n & 255;
                    if (d < NOPE)
                        g_k2[(((size_t)(b * HH + h)) * SS + s) * DQK + d] = pv;
                    else
                        g_v2t[(((size_t)(b * HH + h)) * VD + (d - NOPE)) * SS + s] = pv;
                }
            }
        }
    }
}

// ---------------------------------------------------------------------------
// RoPE on packed arrays
// ---------------------------------------------------------------------------
__global__ void rope_kernel(const float* __restrict__ PE,
                            const float* __restrict__ cosb,
                            const float* __restrict__ sinb) {
    int tt = blockIdx.x * blockDim.x + threadIdx.x;
    if (tt >= BB * SS * 32) return;
    int i = tt & 31;
    int bs = tt >> 5;
    int b = bs / SS, s = bs % SS;

    float c  = cosb[(size_t)bs * ROPE + i];
    float sn = sinb[(size_t)bs * ROPE + i];

    float p1 = PE[(size_t)bs * ROPE + i];
    float p2 = PE[(size_t)bs * ROPE + i + 32];
    uint32_t k1 = bpack(p1 * c - p2 * sn);
    uint32_t k2 = bpack(p2 * c + p1 * sn);

#pragma unroll
    for (int h = 0; h < HH; h++) {
        size_t base = (((size_t)(b * HH + h)) * SS + s) * DQK + NOPE;
        float x1 = bunpack(g_q2[base + i]);
        float x2 = bunpack(g_q2[base + i + 32]);
        g_q2[base + i]      = bpack(x1 * c - x2 * sn);
        g_q2[base + i + 32] = bpack(x2 * c + x1 * sn);
        g_k2[base + i]      = k1;
        g_k2[base + i + 32] = k2;
    }
}

// ---------------------------------------------------------------------------
// Flash attention (causal), split-bf16 mma: BQ=BK=64, 256 threads
// ---------------------------------------------------------------------------
#define QP2 200   // Q/K smem pitch (halfs)
#define VP2 72    // V pitch
#define PP2 72    // P pitch
#define SP2 68    // score pitch (floats)
// ushort part: 4*64*QP2 + 2*128*VP2 + 2*64*PP2 = 51200 + 18432 + 9216 = 78848
// float part:  2*64*SP2 + 192 = 8896
#define FL_SMEM_BYTES (78848*2 + 8896*4)

extern __shared__ unsigned short fsm2[];

__global__ __launch_bounds__(256) void flash_kernel(float* __restrict__ out) {
    const int qt = gridDim.x - 1 - blockIdx.x;   // heavy CTAs first
    const int h = blockIdx.y, b = blockIdx.z;
    const int tid = threadIdx.x;
    const int w = tid >> 5, lane = tid & 31;
    const int g = lane >> 2, t = lane & 3;
    const int lrow = lane & 15, lc8 = (lane >> 4) << 3;

    unsigned short* sQh = fsm2;
    unsigned short* sQl = sQh + 64 * QP2;
    unsigned short* sKh = sQl + 64 * QP2;
    unsigned short* sKl = sKh + 64 * QP2;
    unsigned short* sVh = sKl + 64 * QP2;
    unsigned short* sVl = sVh + 128 * VP2;
    unsigned short* sPh = sVl + 128 * VP2;
    unsigned short* sPl = sPh + 64 * PP2;
    float* sS0 = (float*)(sPl + 64 * PP2);
    float* sS1 = sS0 + 64 * SP2;
    float* sM  = sS1 + 64 * SP2;
    float* sL  = sM + 64;
    float* sA  = sL + 64;

    const uint32_t uQh = smem_u32(sQh), uQl = smem_u32(sQl);
    const uint32_t uKh = smem_u32(sKh), uKl = smem_u32(sKl);
    const uint32_t uVh = smem_u32(sVh), uVl = smem_u32(sVl);
    const uint32_t uPh = smem_u32(sPh), uPl = smem_u32(sPl);

    // score warp mapping: 2m x 2n x 2(k-split 96/96)
    const int khalf = (w & 1) * 96;
    const int smw = ((w >> 1) & 1) * 32;
    const int snw = ((w >> 2) & 1) * 32;
    float* sSp = (w & 1) ? sS1 : sS0;
    // PV warp mapping: 2m x 4n
    const int pmw = (w & 1) * 32;
    const int pnw = (w >> 1) * 32;

    const int q0 = qt * 64;
    const size_t bh = (size_t)(b * HH + h);
    const size_t qbase = (bh * SS + q0) * DQK;

    // load Q tile (packed -> hi/lo)
#pragma unroll
    for (int i = 0; i < 12; i++) {
        int idx = tid + i * 256;
        int r = idx / 48, ch = idx % 48;
        uint4 v = *(const uint4*)&g_q2[qbase + (size_t)r * DQK + ch * 4];
        uint32_t h0 = __byte_perm(v.x, v.y, PERM_HI), l0 = __byte_perm(v.x, v.y, PERM_LO);
        uint32_t h1 = __byte_perm(v.z, v.w, PERM_HI), l1 = __byte_perm(v.z, v.w, PERM_LO);
        int doff = r * QP2 + ch * 4;
        *(uint2*)&sQh[doff] = make_uint2(h0, h1);
        *(uint2*)&sQl[doff] = make_uint2(l0, l1);
    }
    if (tid < 64) { sM[tid] = -1e30f; sL[tid] = 0.f; }

    float po[2][4][4] = {};

    for (int kt = 0; kt <= qt; kt++) {
        const int k0 = kt * 64;
        const size_t kbase = (bh * SS + k0) * DQK;

        __syncthreads();  // everyone done with prev sK/sV/sP/sS
#pragma unroll
        for (int i = 0; i < 12; i++) {
            int idx = tid + i * 256;
            int r = idx / 48, ch = idx % 48;
            uint4 v = *(const uint4*)&g_k2[kbase + (size_t)r * DQK + ch * 4];
            uint32_t h0 = __byte_perm(v.x, v.y, PERM_HI), l0 = __byte_perm(v.x, v.y, PERM_LO);
            uint32_t h1 = __byte_perm(v.z, v.w, PERM_HI), l1 = __byte_perm(v.z, v.w, PERM_LO);
            int doff = r * QP2 + ch * 4;
            *(uint2*)&sKh[doff] = make_uint2(h0, h1);
            *(uint2*)&sKl[doff] = make_uint2(l0, l1);
        }
#pragma unroll
        for (int i = 0; i < 8; i++) {
            int idx = tid + i * 256;
            int r = idx >> 4, ch = idx & 15;
            uint4 v = *(const uint4*)&g_v2t[(bh * VD + r) * SS + k0 + ch * 4];
            uint32_t h0 = __byte_perm(v.x, v.y, PERM_HI), l0 = __byte_perm(v.x, v.y, PERM_LO);
            uint32_t h1 = __byte_perm(v.z, v.w, PERM_HI), l1 = __byte_perm(v.z, v.w, PERM_LO);
            int doff = r * VP2 + ch * 4;
            *(uint2*)&sVh[doff] = make_uint2(h0, h1);
            *(uint2*)&sVl[doff] = make_uint2(l0, l1);
        }
        __syncthreads();

        // ---- scores (k-half per warp) ----
        float sc[2][4][4] = {};
#pragma unroll
        for (int kk = 0; kk < 6; kk++) {
            const int kb = khalf + (kk << 4);
            uint32_t ah[2][4], al[2][4];
#pragma unroll
            for (int mf = 0; mf < 2; mf++) {
                uint32_t off = (uint32_t)(((smw + mf * 16 + lrow) * QP2 + kb + lc8) * 2);
                ldsm4(ah[mf], uQh + off);
                ldsm4(al[mf], uQl + off);
            }
#pragma unroll
            for (int p = 0; p < 2; p++) {
                uint32_t off = (uint32_t)(((snw + p * 16 + lrow) * QP2 + kb + lc8) * 2);
                uint32_t b4h[4], b4l[4];
                ldsm4(b4h, uKh + off);
                ldsm4(b4l, uKl + off);
                uint32_t bhe[2] = {b4h[0], b4h[2]}, bho[2] = {b4h[1], b4h[3]};
                uint32_t ble[2] = {b4l[0], b4l[2]}, blq[2] = {b4l[1], b4l[3]};
#pragma unroll
                for (int mf = 0; mf < 2; mf++) {
                    mma16(sc[mf][2 * p],     ah[mf], bhe);
                    mma16(sc[mf][2 * p],     ah[mf], ble);
                    mma16(sc[mf][2 * p],     al[mf], bhe);
                    mma16(sc[mf][2 * p + 1], ah[mf], bho);
                    mma16(sc[mf][2 * p + 1], ah[mf], blq);
                    mma16(sc[mf][2 * p + 1], al[mf], bho);
                }
            }
        }
#pragma unroll
        for (int mf = 0; mf < 2; mf++) {
            const int r = smw + mf * 16 + g;
#pragma unroll
            for (int nf = 0; nf < 4; nf++) {
                const int cl = snw + nf * 8 + (t << 1);
                *(float2*)&sSp[r * SP2 + cl]       = make_float2(sc[mf][nf][0], sc[mf][nf][1]);
                *(float2*)&sSp[(r + 8) * SP2 + cl] = make_float2(sc[mf][nf][2], sc[mf][nf][3]);
            }
        }
        __syncthreads();

        // ---- online softmax: 4 threads per row ----
        {
            const int r = tid >> 2, sub = tid & 3;
            const int qi = q0 + r;
            const int c0 = sub * 16;
            float vb[16];
            float mx = -1e30f;
#pragma unroll
            for (int j = 0; j < 16; j++) {
                float s = (sS0[r * SP2 + c0 + j] + sS1[r * SP2 + c0 + j]) * SCALE;
                if (k0 + c0 + j > qi) s = -1e30f;
                vb[j] = s;
                mx = fmaxf(mx, s);
            }
            mx = fmaxf(mx, __shfl_xor_sync(0xffffffffu, mx, 1));
            mx = fmaxf(mx, __shfl_xor_sync(0xffffffffu, mx, 2));
            float mo = sM[r];
            mx = fmaxf(mx, mo);
            float sum = 0.f;
#pragma unroll
            for (int j = 0; j < 16; j += 2) {
                float p0 = __expf(vb[j] - mx), p1 = __expf(vb[j + 1] - mx);
                sum += p0 + p1;
                __nv_bfloat16 h0 = __float2bfloat16_rn(p0);
                __nv_bfloat16 h1 = __float2bfloat16_rn(p1);
                __nv_bfloat16 l0 = __float2bfloat16_rn(p0 - __bfloat162float(h0));
                __nv_bfloat16 l1 = __float2bfloat16_rn(p1 - __bfloat162float(h1));
                uint32_t hw = (uint32_t)__bfloat16_as_ushort(h0) | ((uint32_t)__bfloat16_as_ushort(h1) << 16);
                uint32_t lw = (uint32_t)__bfloat16_as_ushort(l0) | ((uint32_t)__bfloat16_as_ushort(l1) << 16);
                *(uint32_t*)&sPh[r * PP2 + c0 + j] = hw;
                *(uint32_t*)&sPl[r * PP2 + c0 + j] = lw;
            }
            sum += __shfl_xor_sync(0xffffffffu, sum, 1);
            sum += __shfl_xor_sync(0xffffffffu, sum, 2);
            if (sub == 0) {
                float alpha = __expf(mo - mx);
                sL[r] = alpha * sL[r] + sum;
                sM[r] = mx;
                sA[r] = alpha;
            }
        }
        __syncthreads();

        // ---- PV: po = alpha*po + P @ V ----
#pragma unroll
        for (int mf = 0; mf < 2; mf++) {
            const float aa = sA[pmw + mf * 16 + g];
            const float ab = sA[pmw + mf * 16 + g + 8];
#pragma unroll
            for (int nf = 0; nf < 4; nf++) {
                po[mf][nf][0] *= aa; po[mf][nf][1] *= aa;
                po[mf][nf][2] *= ab; po[mf][nf][3] *= ab;
            }
        }
#pragma unroll
        for (int kk = 0; kk < 4; kk++) {
            const int kb = kk << 4;
            uint32_t ah[2][4], al[2][4];
#pragma unroll
            for (int mf = 0; mf < 2; mf++) {
                uint32_t off = (uint32_t)(((pmw + mf * 16 + lrow) * PP2 + kb + lc8) * 2);
                ldsm4(ah[mf], uPh + off);
                ldsm4(al[mf], uPl + off);
            }
#pragma unroll
            for (int p = 0; p < 2; p++) {
                uint32_t off = (uint32_t)(((pnw + p * 16 + lrow) * VP2 + kb + lc8) * 2);
                uint32_t b4h[4], b4l[4];
                ldsm4(b4h, uVh + off);
                ldsm4(b4l, uVl + off);
                uint32_t bhe[2] = {b4h[0], b4h[2]}, bho[2] = {b4h[1], b4h[3]};
                uint32_t ble[2] = {b4l[0], b4l[2]}, blq[2] = {b4l[1], b4l[3]};
#pragma unroll
                for (int mf = 0; mf < 2; mf++) {
                    mma16(po[mf][2 * p],     ah[mf], bhe);
                    mma16(po[mf][2 * p],     ah[mf], ble);
                    mma16(po[mf][2 * p],     al[mf], bhe);
                    mma16(po[mf][2 * p + 1], ah[mf], bho);
                    mma16(po[mf][2 * p + 1], ah[mf], blq);
                    mma16(po[mf][2 * p + 1], al[mf], bho);
                }
            }
        }
    }

    // epilogue: out[b, q, h, d]
#pragma unroll
    for (int mf = 0; mf < 2; mf++) {
        const int r = pmw + mf * 16 + g;
        const float iv0 = 1.f / sL[r];
        const float iv1 = 1.f / sL[r + 8];
        const size_t ob0 = (((size_t)b * SS + q0 + r) * HH + h) * VD;
        const size_t ob1 = (((size_t)b * SS + q0 + r + 8) * HH + h) * VD;
#pragma unroll
        for (int nf = 0; nf < 4; nf++) {
            const int cl = pnw + nf * 8 + (t << 1);
            *(float2*)&out[ob0 + cl] = make_float2(po[mf][nf][0] * iv0, po[mf][nf][1] * iv0);
            *(float2*)&out[ob1 + cl] = make_float2(po[mf][nf][2] * iv1, po[mf][nf][3] * iv1);
        }
    }
}

// ---------------------------------------------------------------------------
extern "C" void kernel_launch(void* const* d_in, const int* in_sizes, int n_in,
                              void* d_out, int out_size) {
    const float* Q    = (const float*)d_in[0];
    const float* KV   = (const float*)d_in[1];
    const float* PE   = (const float*)d_in[2];
    const float* WUQ  = (const float*)d_in[3];
    const float* WUKV = (const float*)d_in[4];
    const float* cosb = (const float*)d_in[5];
    const float* sinb = (const float*)d_in[6];
    float* out = (float*)d_out;
    (void)in_sizes; (void)n_in; (void)out_size;

    cudaFuncSetAttribute(flash_kernel, cudaFuncAttributeMaxDynamicSharedMemorySize,
                         FL_SMEM_BYTES);

    dim3 g1(NQ / 128, MM / 128);   // (24, 32)
    gemm_mma_kernel<0><<<g1, 256>>>(Q, WUQ, QR);

    dim3 g2(NKV / 128, MM / 128);  // (32, 32)
    gemm_mma_kernel<1><<<g2, 256>>>(KV, WUKV, KVR);

    int nrope = BB * SS * 32;
    rope_kernel<<<(nrope + 255) / 256, 256>>>(PE, cosb, sinb);

    dim3 gf(SS / 64, HH, BB);      // (32, 16, 2)
    flash_kernel<<<gf, 256, FL_SMEM_BYTES>>>(out);
}

// round 7
// speedup vs baseline: 5.8551x; 1.1867x over previous
#include <cuda_runtime.h>
#include <cuda_bf16.h>
#include <math.h>
#include <stdint.h>

#define BB 2
#define SS 2048
#define HH 16
#define NOPE 128
#define ROPE 64
#define VD 128
#define DQK 192           // NOPE + ROPE
#define QR 1536
#define KVR 512
#define NQ (HH*DQK)       // 3072
#define NKV (HH*(NOPE+VD))// 4096
#define MM (BB*SS)        // 4096
#define SCALE 0.07216878364870323f  // 1/sqrt(192)

// Packed split-bf16 scratch: each uint32 = (hi_bf16 | lo_bf16<<16), x = hi + lo
__device__ uint32_t g_q2[(size_t)BB*HH*SS*DQK];   // [b,h,s,192]
__device__ uint32_t g_k2[(size_t)BB*HH*SS*DQK];   // [b,h,s,192]
__device__ uint32_t g_v2t[(size_t)BB*HH*VD*SS];   // [b,h,d,s]  (transposed)

// ---------------------------------------------------------------------------
// helpers
// ---------------------------------------------------------------------------
__device__ __forceinline__ uint32_t smem_u32(const void* p) {
    uint32_t a;
    asm("{ .reg .u64 t; cvta.to.shared.u64 t, %1; cvt.u32.u64 %0, t; }" : "=r"(a) : "l"(p));
    return a;
}
__device__ __forceinline__ void ldsm4(uint32_t* r, uint32_t addr) {
    asm volatile("ldmatrix.sync.aligned.m8n8.x4.shared.b16 {%0,%1,%2,%3}, [%4];"
                 : "=r"(r[0]), "=r"(r[1]), "=r"(r[2]), "=r"(r[3]) : "r"(addr));
}
__device__ __forceinline__ void mma16(float* c, const uint32_t* a, const uint32_t* b) {
    asm volatile("mma.sync.aligned.m16n8k16.row.col.f32.bf16.bf16.f32 "
                 "{%0,%1,%2,%3}, {%4,%5,%6,%7}, {%8,%9}, {%0,%1,%2,%3};"
                 : "+f"(c[0]), "+f"(c[1]), "+f"(c[2]), "+f"(c[3])
                 : "r"(a[0]), "r"(a[1]), "r"(a[2]), "r"(a[3]), "r"(b[0]), "r"(b[1]));
}
__device__ __forceinline__ uint32_t bpack(float x) {
    __nv_bfloat16 h = __float2bfloat16_rn(x);
    float r = x - __bfloat162float(h);
    __nv_bfloat16 l = __float2bfloat16_rn(r);
    return (uint32_t)__bfloat16_as_ushort(h) | ((uint32_t)__bfloat16_as_ushort(l) << 16);
}
__device__ __forceinline__ float bunpack(uint32_t u) {
    return __bfloat162float(__ushort_as_bfloat16((unsigned short)(u & 0xffffu)))
         + __bfloat162float(__ushort_as_bfloat16((unsigned short)(u >> 16)));
}
// pack (x,y) to hi-pair + lo-pair bf16x2 regs
__device__ __forceinline__ void pack_hl(float x, float y, uint32_t& hi, uint32_t& lo) {
    __nv_bfloat162 h = __floats2bfloat162_rn(x, y);
    float rx = x - __bfloat162float(h.x);
    float ry = y - __bfloat162float(h.y);
    __nv_bfloat162 l = __floats2bfloat162_rn(rx, ry);
    hi = *(uint32_t*)&h;
    lo = *(uint32_t*)&l;
}
#define PERM_HI 0x5410
#define PERM_LO 0x7632

// ---------------------------------------------------------------------------
// GEMM (split-bf16, 3-term): C[m,n] = sum_k A[m,k]*W[n,k]
// CTA 128x128, warp 32x64, K-chunk 32, register prefetch of next chunk.
// MODE 0 -> g_q2 ; MODE 1 -> g_k2/g_v2t
// ---------------------------------------------------------------------------
#define GP 40   // smem row pitch (halfs)

__device__ __forceinline__ void split_store4(unsigned short* H, unsigned short* L,
                                             int off, float4 v) {
    __nv_bfloat16 h0 = __float2bfloat16_rn(v.x), h1 = __float2bfloat16_rn(v.y);
    __nv_bfloat16 h2 = __float2bfloat16_rn(v.z), h3 = __float2bfloat16_rn(v.w);
    ushort4 hh;
    hh.x = __bfloat16_as_ushort(h0); hh.y = __bfloat16_as_ushort(h1);
    hh.z = __bfloat16_as_ushort(h2); hh.w = __bfloat16_as_ushort(h3);
    *(ushort4*)(H + off) = hh;
    ushort4 ll;
    ll.x = __bfloat16_as_ushort(__float2bfloat16_rn(v.x - __bfloat162float(h0)));
    ll.y = __bfloat16_as_ushort(__float2bfloat16_rn(v.y - __bfloat162float(h1)));
    ll.z = __bfloat16_as_ushort(__float2bfloat16_rn(v.z - __bfloat162float(h2)));
    ll.w = __bfloat16_as_ushort(__float2bfloat16_rn(v.w - __bfloat162float(h3)));
    *(ushort4*)(L + off) = ll;
}

template<int MODE>
__global__ __launch_bounds__(256) void gemm_mma_kernel(const float* __restrict__ A,
                                                       const float* __restrict__ W,
                                                       int K) {
    __shared__ unsigned short Ah[128 * GP], Al[128 * GP], Wh[128 * GP], Wl[128 * GP];
    const int tid = threadIdx.x;
    const int w = tid >> 5, lane = tid & 31;
    const int g = lane >> 2, t = lane & 3;
    const int lrow = lane & 15, lc8 = (lane >> 4) << 3;
    const int bm = blockIdx.y * 128, bn = blockIdx.x * 128;
    const int mw = (w >> 1) * 32, nw = (w & 1) * 64;
    const uint32_t uAh = smem_u32(Ah), uAl = smem_u32(Al);
    const uint32_t uWh = smem_u32(Wh), uWl = smem_u32(Wl);

    float c[2][8][4] = {};
    float4 ra[4], rb[4];
    int rr[4], rf[4];
#pragma unroll
    for (int i = 0; i < 4; i++) {
        int idx = tid + i * 256;
        rr[i] = idx >> 3; rf[i] = (idx & 7) << 2;
        ra[i] = *(const float4*)&A[(size_t)(bm + rr[i]) * K + rf[i]];
        rb[i] = *(const float4*)&W[(size_t)(bn + rr[i]) * K + rf[i]];
    }

    for (int k0 = 0; k0 < K; k0 += 32) {
#pragma unroll
        for (int i = 0; i < 4; i++) {
            split_store4(Ah, Al, rr[i] * GP + rf[i], ra[i]);
            split_store4(Wh, Wl, rr[i] * GP + rf[i], rb[i]);
        }
        __syncthreads();
        if (k0 + 32 < K) {
#pragma unroll
            for (int i = 0; i < 4; i++) {
                ra[i] = *(const float4*)&A[(size_t)(bm + rr[i]) * K + k0 + 32 + rf[i]];
                rb[i] = *(const float4*)&W[(size_t)(bn + rr[i]) * K + k0 + 32 + rf[i]];
            }
        }

#pragma unroll
        for (int kk = 0; kk < 2; kk++) {
            const int kb = kk << 4;
            uint32_t ah[2][4], al[2][4];
#pragma unroll
            for (int mf = 0; mf < 2; mf++) {
                uint32_t off = (uint32_t)(((mw + mf * 16 + lrow) * GP + kb + lc8) * 2);
                ldsm4(ah[mf], uAh + off);
                ldsm4(al[mf], uAl + off);
            }
#pragma unroll
            for (int p = 0; p < 4; p++) {
                uint32_t off = (uint32_t)(((nw + p * 16 + lrow) * GP + kb + lc8) * 2);
                uint32_t b4h[4], b4l[4];
                ldsm4(b4h, uWh + off);
                ldsm4(b4l, uWl + off);
                uint32_t bhe[2] = {b4h[0], b4h[2]}, bho[2] = {b4h[1], b4h[3]};
                uint32_t ble[2] = {b4l[0], b4l[2]}, blq[2] = {b4l[1], b4l[3]};
#pragma unroll
                for (int mf = 0; mf < 2; mf++) {
                    mma16(c[mf][2 * p],     ah[mf], bhe);
                    mma16(c[mf][2 * p],     ah[mf], ble);
                    mma16(c[mf][2 * p],     al[mf], bhe);
                    mma16(c[mf][2 * p + 1], ah[mf], bho);
                    mma16(c[mf][2 * p + 1], ah[mf], blq);
                    mma16(c[mf][2 * p + 1], al[mf], bho);
                }
            }
        }
        __syncthreads();
    }

#pragma unroll
    for (int mf = 0; mf < 2; mf++) {
#pragma unroll
        for (int i = 0; i < 4; i++) {
            const int m = bm + mw + mf * 16 + g + ((i >> 1) << 3);
            const int b = m >> 11, s = m & 2047;
#pragma unroll
            for (int nf = 0; nf < 8; nf++) {
                const int n = bn + nw + nf * 8 + (t << 1) + (i & 1);
                const uint32_t pv = bpack(c[mf][nf][i]);
                if (MODE == 0) {
                    const int h = n / DQK, d = n % DQK;
                    g_q2[(((size_t)(b * HH + h)) * SS + s) * DQK + d] = pv;
                } else {
                    const int h = n >> 8, d = n & 255;
                    if (d < NOPE)
                        g_k2[(((size_t)(b * HH + h)) * SS + s) * DQK + d] = pv;
                    else
                        g_v2t[(((size_t)(b * HH + h)) * VD + (d - NOPE)) * SS + s] = pv;
                }
            }
        }
    }
}

// ---------------------------------------------------------------------------
// RoPE on packed arrays
// ---------------------------------------------------------------------------
__global__ void rope_kernel(const float* __restrict__ PE,
                            const float* __restrict__ cosb,
                            const float* __restrict__ sinb) {
    int tt = blockIdx.x * blockDim.x + threadIdx.x;
    if (tt >= BB * SS * 32) return;
    int i = tt & 31;
    int bs = tt >> 5;
    int b = bs / SS, s = bs % SS;

    float c  = cosb[(size_t)bs * ROPE + i];
    float sn = sinb[(size_t)bs * ROPE + i];

    float p1 = PE[(size_t)bs * ROPE + i];
    float p2 = PE[(size_t)bs * ROPE + i + 32];
    uint32_t k1 = bpack(p1 * c - p2 * sn);
    uint32_t k2 = bpack(p2 * c + p1 * sn);

#pragma unroll
    for (int h = 0; h < HH; h++) {
        size_t base = (((size_t)(b * HH + h)) * SS + s) * DQK + NOPE;
        float x1 = bunpack(g_q2[base + i]);
        float x2 = bunpack(g_q2[base + i + 32]);
        g_q2[base + i]      = bpack(x1 * c - x2 * sn);
        g_q2[base + i + 32] = bpack(x2 * c + x1 * sn);
        g_k2[base + i]      = k1;
        g_k2[base + i + 32] = k2;
    }
}

// ---------------------------------------------------------------------------
// Flash attention (causal): BQ=128, BK=64, 256 threads (8 warps x m16),
// register softmax + C->A fragment repack (scores/P never touch smem).
// ---------------------------------------------------------------------------
#define QP2 200   // Q/K smem pitch (halfs)
#define VP2 72    // V pitch (halfs)
// smem halfs: Qh/Ql 128*200 each, Kh/Kl 64*200 each, Vh/Vl 128*72 each
#define FL_SMEM_BYTES ((2*128*QP2 + 2*64*QP2 + 2*128*VP2) * 2)

extern __shared__ unsigned short fsm2[];

__global__ __launch_bounds__(256, 1) void flash_kernel(float* __restrict__ out) {
    const int qt = gridDim.x - 1 - blockIdx.x;   // heavy CTAs first
    const int h = blockIdx.y, b = blockIdx.z;
    const int tid = threadIdx.x;
    const int w = tid >> 5, lane = tid & 31;
    const int g = lane >> 2, t = lane & 3;
    const int lrow = lane & 15, lc8 = (lane >> 4) << 3;

    unsigned short* sQh = fsm2;
    unsigned short* sQl = sQh + 128 * QP2;
    unsigned short* sKh = sQl + 128 * QP2;
    unsigned short* sKl = sKh + 64 * QP2;
    unsigned short* sVh = sKl + 64 * QP2;
    unsigned short* sVl = sVh + 128 * VP2;

    const uint32_t uQh = smem_u32(sQh), uQl = smem_u32(sQl);
    const uint32_t uKh = smem_u32(sKh), uKl = smem_u32(sKl);
    const uint32_t uVh = smem_u32(sVh), uVl = smem_u32(sVl);

    const int wm = w * 16;          // this warp's q-row slab
    const int q0 = qt * 128;
    const size_t bh = (size_t)(b * HH + h);
    const size_t qbase = (bh * SS + q0) * DQK;

    // load Q tile 128x192 (packed -> hi/lo)
#pragma unroll
    for (int i = 0; i < 24; i++) {
        int idx = tid + i * 256;
        int r = idx / 48, ch = idx % 48;
        uint4 v = *(const uint4*)&g_q2[qbase + (size_t)r * DQK + ch * 4];
        uint32_t h0 = __byte_perm(v.x, v.y, PERM_HI), l0 = __byte_perm(v.x, v.y, PERM_LO);
        uint32_t h1 = __byte_perm(v.z, v.w, PERM_HI), l1 = __byte_perm(v.z, v.w, PERM_LO);
        int doff = r * QP2 + ch * 4;
        *(uint2*)&sQh[doff] = make_uint2(h0, h1);
        *(uint2*)&sQl[doff] = make_uint2(l0, l1);
    }

    const int r0g = q0 + wm + g;        // this thread's two q rows
    const int r1g = r0g + 8;

    float po[16][4] = {};
    float m0 = -1e30f, m1 = -1e30f, l0 = 0.f, l1 = 0.f;

    const int nkt = 2 * (qt + 1);
    for (int kt = 0; kt < nkt; kt++) {
        const int k0 = kt * 64;
        const size_t kbase = (bh * SS + k0) * DQK;

        __syncthreads();
#pragma unroll
        for (int i = 0; i < 12; i++) {
            int idx = tid + i * 256;
            int r = idx / 48, ch = idx % 48;
            uint4 v = *(const uint4*)&g_k2[kbase + (size_t)r * DQK + ch * 4];
            uint32_t h0 = __byte_perm(v.x, v.y, PERM_HI), lo0 = __byte_perm(v.x, v.y, PERM_LO);
            uint32_t h1 = __byte_perm(v.z, v.w, PERM_HI), lo1 = __byte_perm(v.z, v.w, PERM_LO);
            int doff = r * QP2 + ch * 4;
            *(uint2*)&sKh[doff] = make_uint2(h0, h1);
            *(uint2*)&sKl[doff] = make_uint2(lo0, lo1);
        }
#pragma unroll
        for (int i = 0; i < 8; i++) {
            int idx = tid + i * 256;
            int r = idx >> 4, ch = idx & 15;
            uint4 v = *(const uint4*)&g_v2t[(bh * VD + r) * SS + k0 + ch * 4];
            uint32_t h0 = __byte_perm(v.x, v.y, PERM_HI), lo0 = __byte_perm(v.x, v.y, PERM_LO);
            uint32_t h1 = __byte_perm(v.z, v.w, PERM_HI), lo1 = __byte_perm(v.z, v.w, PERM_LO);
            int doff = r * VP2 + ch * 4;
            *(uint2*)&sVh[doff] = make_uint2(h0, h1);
            *(uint2*)&sVl[doff] = make_uint2(lo0, lo1);
        }
        __syncthreads();

        // ---- scores: warp's 16 rows x 64 cols, full k=192 ----
        float sc[8][4] = {};
#pragma unroll
        for (int kk = 0; kk < 12; kk++) {
            const int kb = kk << 4;
            uint32_t ah[4], al[4];
            uint32_t off = (uint32_t)(((wm + lrow) * QP2 + kb + lc8) * 2);
            ldsm4(ah, uQh + off);
            ldsm4(al, uQl + off);
#pragma unroll
            for (int p = 0; p < 4; p++) {
                uint32_t koff = (uint32_t)(((p * 16 + lrow) * QP2 + kb + lc8) * 2);
                uint32_t b4h[4], b4l[4];
                ldsm4(b4h, uKh + koff);
                ldsm4(b4l, uKl + koff);
                uint32_t bhe[2] = {b4h[0], b4h[2]}, bho[2] = {b4h[1], b4h[3]};
                uint32_t ble[2] = {b4l[0], b4l[2]}, blq[2] = {b4l[1], b4l[3]};
                mma16(sc[2 * p],     ah, bhe);
                mma16(sc[2 * p],     ah, ble);
                mma16(sc[2 * p],     al, bhe);
                mma16(sc[2 * p + 1], ah, bho);
                mma16(sc[2 * p + 1], ah, blq);
                mma16(sc[2 * p + 1], al, bho);
            }
        }

        // ---- mask + scale + register online softmax ----
        const bool needmask = (k0 + 63 > r0g);
        float mx0 = -1e30f, mx1 = -1e30f;
#pragma unroll
        for (int nf = 0; nf < 8; nf++) {
            const int c0 = k0 + nf * 8 + (t << 1);
            if (needmask) {
                sc[nf][0] = (c0     > r0g) ? -1e30f : sc[nf][0] * SCALE;
                sc[nf][1] = (c0 + 1 > r0g) ? -1e30f : sc[nf][1] * SCALE;
                sc[nf][2] = (c0     > r1g) ? -1e30f : sc[nf][2] * SCALE;
                sc[nf][3] = (c0 + 1 > r1g) ? -1e30f : sc[nf][3] * SCALE;
            } else {
                sc[nf][0] *= SCALE; sc[nf][1] *= SCALE;
                sc[nf][2] *= SCALE; sc[nf][3] *= SCALE;
            }
            mx0 = fmaxf(mx0, fmaxf(sc[nf][0], sc[nf][1]));
            mx1 = fmaxf(mx1, fmaxf(sc[nf][2], sc[nf][3]));
        }
        mx0 = fmaxf(mx0, __shfl_xor_sync(0xffffffffu, mx0, 1));
        mx0 = fmaxf(mx0, __shfl_xor_sync(0xffffffffu, mx0, 2));
        mx1 = fmaxf(mx1, __shfl_xor_sync(0xffffffffu, mx1, 1));
        mx1 = fmaxf(mx1, __shfl_xor_sync(0xffffffffu, mx1, 2));
        mx0 = fmaxf(mx0, m0);
        mx1 = fmaxf(mx1, m1);
        const float al0 = __expf(m0 - mx0);
        const float al1 = __expf(m1 - mx1);
        m0 = mx0; m1 = mx1;

        // exp + pack P into A-fragments (hi/lo), accumulate sums
        uint32_t pah[4][4], pal[4][4];
        float s0 = 0.f, s1 = 0.f;
#pragma unroll
        for (int j = 0; j < 4; j++) {
            float p00 = __expf(sc[2 * j][0] - mx0), p01 = __expf(sc[2 * j][1] - mx0);
            float p10 = __expf(sc[2 * j][2] - mx1), p11 = __expf(sc[2 * j][3] - mx1);
            float q00 = __expf(sc[2 * j + 1][0] - mx0), q01 = __expf(sc[2 * j + 1][1] - mx0);
            float q10 = __expf(sc[2 * j + 1][2] - mx1), q11 = __expf(sc[2 * j + 1][3] - mx1);
            s0 += p00 + p01 + q00 + q01;
            s1 += p10 + p11 + q10 + q11;
            pack_hl(p00, p01, pah[j][0], pal[j][0]);
            pack_hl(p10, p11, pah[j][1], pal[j][1]);
            pack_hl(q00, q01, pah[j][2], pal[j][2]);
            pack_hl(q10, q11, pah[j][3], pal[j][3]);
        }
        s0 += __shfl_xor_sync(0xffffffffu, s0, 1);
        s0 += __shfl_xor_sync(0xffffffffu, s0, 2);
        s1 += __shfl_xor_sync(0xffffffffu, s1, 1);
        s1 += __shfl_xor_sync(0xffffffffu, s1, 2);
        l0 = l0 * al0 + s0;
        l1 = l1 * al1 + s1;

        // ---- PV: po = alpha*po + P @ V-frags ----
#pragma unroll
        for (int nf = 0; nf < 16; nf++) {
            po[nf][0] *= al0; po[nf][1] *= al0;
            po[nf][2] *= al1; po[nf][3] *= al1;
        }
#pragma unroll
        for (int j = 0; j < 4; j++) {
            const int kb = j << 4;
#pragma unroll
            for (int p = 0; p < 8; p++) {
                uint32_t voff = (uint32_t)(((p * 16 + lrow) * VP2 + kb + lc8) * 2);
                uint32_t b4h[4], b4l[4];
                ldsm4(b4h, uVh + voff);
                ldsm4(b4l, uVl + voff);
                uint32_t bhe[2] = {b4h[0], b4h[2]}, bho[2] = {b4h[1], b4h[3]};
                uint32_t ble[2] = {b4l[0], b4l[2]}, blq[2] = {b4l[1], b4l[3]};
                mma16(po[2 * p],     pah[j], bhe);
                mma16(po[2 * p],     pah[j], ble);
                mma16(po[2 * p],     pal[j], bhe);
                mma16(po[2 * p + 1], pah[j], bho);
                mma16(po[2 * p + 1], pah[j], blq);
                mma16(po[2 * p + 1], pal[j], bho);
            }
        }
    }

    // epilogue: out[b, q, h, d]
    {
        const float iv0 = 1.f / l0;
        const float iv1 = 1.f / l1;
        const size_t ob0 = (((size_t)b * SS + r0g) * HH + h) * VD;
        const size_t ob1 = (((size_t)b * SS + r1g) * HH + h) * VD;
#pragma unroll
        for (int nf = 0; nf < 16; nf++) {
            const int cl = nf * 8 + (t << 1);
            *(float2*)&out[ob0 + cl] = make_float2(po[nf][0] * iv0, po[nf][1] * iv0);
            *(float2*)&out[ob1 + cl] = make_float2(po[nf][2] * iv1, po[nf][3] * iv1);
        }
    }
}

// ---------------------------------------------------------------------------
extern "C" void kernel_launch(void* const* d_in, const int* in_sizes, int n_in,
                              void* d_out, int out_size) {
    const float* Q    = (const float*)d_in[0];
    const float* KV   = (const float*)d_in[1];
    const float* PE   = (const float*)d_in[2];
    const float* WUQ  = (const float*)d_in[3];
    const float* WUKV = (const float*)d_in[4];
    const float* cosb = (const float*)d_in[5];
    const float* sinb = (const float*)d_in[6];
    float* out = (float*)d_out;
    (void)in_sizes; (void)n_in; (void)out_size;

    cudaFuncSetAttribute(flash_kernel, cudaFuncAttributeMaxDynamicSharedMemorySize,
                         FL_SMEM_BYTES);

    dim3 g1(NQ / 128, MM / 128);   // (24, 32)
    gemm_mma_kernel<0><<<g1, 256>>>(Q, WUQ, QR);

    dim3 g2(NKV / 128, MM / 128);  // (32, 32)
    gemm_mma_kernel<1><<<g2, 256>>>(KV, WUKV, KVR);

    int nrope = BB * SS * 32;
    rope_kernel<<<(nrope + 255) / 256, 256>>>(PE, cosb, sinb);

    dim3 gf(SS / 128, HH, BB);     // (16, 16, 2)
    flash_kernel<<<gf, 256, FL_SMEM_BYTES>>>(out);
}

// round 8
// speedup vs baseline: 6.2346x; 1.0648x over previous
#include <cuda_runtime.h>
#include <cuda_bf16.h>
#include <math.h>
#include <stdint.h>

#define BB 2
#define SS 2048
#define HH 16
#define NOPE 128
#define ROPE 64
#define VD 128
#define DQK 192           // NOPE + ROPE
#define QR 1536
#define KVR 512
#define NQ (HH*DQK)       // 3072
#define NKV (HH*(NOPE+VD))// 4096
#define MM (BB*SS)        // 4096
#define SCALE 0.07216878364870323f  // 1/sqrt(192)

// Packed split-bf16: each uint32 = (hi_bf16 | lo_bf16<<16), x = hi + lo
__device__ uint32_t g_q2[(size_t)BB*HH*SS*DQK];   // [b,h,s,192]
__device__ uint32_t g_k2[(size_t)BB*HH*SS*DQK];   // [b,h,s,192]
__device__ uint32_t g_v2t[(size_t)BB*HH*VD*SS];   // [b,h,d,s]  (transposed)
// pre-split inputs/weights
__device__ uint32_t g_qs[(size_t)MM*QR];
__device__ uint32_t g_kvs[(size_t)MM*KVR];
__device__ uint32_t g_wuqs[(size_t)NQ*QR];
__device__ uint32_t g_wukvs[(size_t)NKV*KVR];

// ---------------------------------------------------------------------------
// helpers
// ---------------------------------------------------------------------------
__device__ __forceinline__ uint32_t smem_u32(const void* p) {
    uint32_t a;
    asm("{ .reg .u64 t; cvta.to.shared.u64 t, %1; cvt.u32.u64 %0, t; }" : "=r"(a) : "l"(p));
    return a;
}
__device__ __forceinline__ void ldsm4(uint32_t* r, uint32_t addr) {
    asm volatile("ldmatrix.sync.aligned.m8n8.x4.shared.b16 {%0,%1,%2,%3}, [%4];"
                 : "=r"(r[0]), "=r"(r[1]), "=r"(r[2]), "=r"(r[3]) : "r"(addr));
}
__device__ __forceinline__ void mma16(float* c, const uint32_t* a, const uint32_t* b) {
    asm volatile("mma.sync.aligned.m16n8k16.row.col.f32.bf16.bf16.f32 "
                 "{%0,%1,%2,%3}, {%4,%5,%6,%7}, {%8,%9}, {%0,%1,%2,%3};"
                 : "+f"(c[0]), "+f"(c[1]), "+f"(c[2]), "+f"(c[3])
                 : "r"(a[0]), "r"(a[1]), "r"(a[2]), "r"(a[3]), "r"(b[0]), "r"(b[1]));
}
__device__ __forceinline__ uint32_t bpack(float x) {
    __nv_bfloat16 h = __float2bfloat16_rn(x);
    float r = x - __bfloat162float(h);
    __nv_bfloat16 l = __float2bfloat16_rn(r);
    return (uint32_t)__bfloat16_as_ushort(h) | ((uint32_t)__bfloat16_as_ushort(l) << 16);
}
__device__ __forceinline__ float bunpack(uint32_t u) {
    return __bfloat162float(__ushort_as_bfloat16((unsigned short)(u & 0xffffu)))
         + __bfloat162float(__ushort_as_bfloat16((unsigned short)(u >> 16)));
}
__device__ __forceinline__ void pack_hl(float x, float y, uint32_t& hi, uint32_t& lo) {
    __nv_bfloat162 h = __floats2bfloat162_rn(x, y);
    float rx = x - __bfloat162float(h.x);
    float ry = y - __bfloat162float(h.y);
    __nv_bfloat162 l = __floats2bfloat162_rn(rx, ry);
    hi = *(uint32_t*)&h;
    lo = *(uint32_t*)&l;
}
#define PERM_HI 0x5410
#define PERM_LO 0x7632

// ---------------------------------------------------------------------------
// pre-split: float -> packed split-bf16.  WHICH selects the destination global.
// ---------------------------------------------------------------------------
template<int WHICH>
__global__ void presplit_kernel(const float* __restrict__ src, int n4) {
    int i = blockIdx.x * blockDim.x + threadIdx.x;
    if (i >= n4) return;
    uint32_t* dst = (WHICH == 0) ? g_qs : (WHICH == 1) ? g_kvs
                  : (WHICH == 2) ? g_wuqs : g_wukvs;
    float4 v = ((const float4*)src)[i];
    uint4 o;
    o.x = bpack(v.x); o.y = bpack(v.y); o.z = bpack(v.z); o.w = bpack(v.w);
    ((uint4*)dst)[i] = o;
}

// ---------------------------------------------------------------------------
// GEMM (split-bf16, 3-term): C[m,n] = sum_k A[m,k]*W[n,k]
// CTA 128x128, 512 threads (16 warps, 4m x 4n, warp 32x32), K-chunk 32,
// 2-stage smem double buffer, packed inputs unpacked via byte_perm.
// MODE 0: g_qs x g_wuqs -> g_q2 ; MODE 1: g_kvs x g_wukvs -> g_k2/g_v2t
// ---------------------------------------------------------------------------
#define GP 40                 // smem row pitch (halfs)
#define GTILE (128*GP)        // halfs per tile (5120) = 10240 B
#define GSTAGE (4*GTILE*2)    // bytes per stage = 40960
#define GSMEM_TOTAL (2*GSTAGE)

extern __shared__ char gsm[];

template<int MODE>
__global__ __launch_bounds__(512) void gemm_mma_kernel() {
    const uint32_t* A = (MODE == 0) ? g_qs : g_kvs;
    const uint32_t* W = (MODE == 0) ? g_wuqs : g_wukvs;
    const int K = (MODE == 0) ? QR : KVR;

    const int tid = threadIdx.x;
    const int w = tid >> 5, lane = tid & 31;
    const int g = lane >> 2, t = lane & 3;
    const int lrow = lane & 15, lc8 = (lane >> 4) << 3;
    const int bm = blockIdx.y * 128, bn = blockIdx.x * 128;
    const int mw = (w >> 2) * 32, nw = (w & 3) * 32;
    const uint32_t uS = smem_u32(gsm);

    // copy mapping: 2 uint4 (8 packed elems) per thread per tile
    int rr[2], rf[2];
#pragma unroll
    for (int i = 0; i < 2; i++) {
        int idx = tid + i * 512;
        rr[i] = idx >> 3; rf[i] = (idx & 7) << 2;
    }

    auto store_stage = [&](int s, const uint4* va, const uint4* vb) {
        unsigned short* pAh = (unsigned short*)(gsm + s * GSTAGE);
        unsigned short* pAl = pAh + GTILE;
        unsigned short* pWh = pAl + GTILE;
        unsigned short* pWl = pWh + GTILE;
#pragma unroll
        for (int i = 0; i < 2; i++) {
            const int off = rr[i] * GP + rf[i];
            uint32_t h0 = __byte_perm(va[i].x, va[i].y, PERM_HI);
            uint32_t l0 = __byte_perm(va[i].x, va[i].y, PERM_LO);
            uint32_t h1 = __byte_perm(va[i].z, va[i].w, PERM_HI);
            uint32_t l1 = __byte_perm(va[i].z, va[i].w, PERM_LO);
            *(uint2*)&pAh[off] = make_uint2(h0, h1);
            *(uint2*)&pAl[off] = make_uint2(l0, l1);
            h0 = __byte_perm(vb[i].x, vb[i].y, PERM_HI);
            l0 = __byte_perm(vb[i].x, vb[i].y, PERM_LO);
            h1 = __byte_perm(vb[i].z, vb[i].w, PERM_HI);
            l1 = __byte_perm(vb[i].z, vb[i].w, PERM_LO);
            *(uint2*)&pWh[off] = make_uint2(h0, h1);
            *(uint2*)&pWl[off] = make_uint2(l0, l1);
        }
    };

    float c[2][4][4] = {};
    uint4 ra[2], rb[2];
#pragma unroll
    for (int i = 0; i < 2; i++) {
        ra[i] = *(const uint4*)&A[(size_t)(bm + rr[i]) * K + rf[i]];
        rb[i] = *(const uint4*)&W[(size_t)(bn + rr[i]) * K + rf[i]];
    }
    store_stage(0, ra, rb);
    __syncthreads();

    const int nc = K >> 5;
    for (int cc = 0; cc < nc; cc++) {
        const int s = cc & 1;
        if (cc + 1 < nc) {
            const int k0 = (cc + 1) << 5;
#pragma unroll
            for (int i = 0; i < 2; i++) {
                ra[i] = *(const uint4*)&A[(size_t)(bm + rr[i]) * K + k0 + rf[i]];
                rb[i] = *(const uint4*)&W[(size_t)(bn + rr[i]) * K + k0 + rf[i]];
            }
        }

        const uint32_t uAh = uS + s * GSTAGE;
        const uint32_t uAl = uAh + GTILE * 2;
        const uint32_t uWh = uAl + GTILE * 2;
        const uint32_t uWl = uWh + GTILE * 2;
#pragma unroll
        for (int kk = 0; kk < 2; kk++) {
            const int kb = kk << 4;
            uint32_t ah[2][4], al[2][4];
#pragma unroll
            for (int mf = 0; mf < 2; mf++) {
                uint32_t off = (uint32_t)(((mw + mf * 16 + lrow) * GP + kb + lc8) * 2);
                ldsm4(ah[mf], uAh + off);
                ldsm4(al[mf], uAl + off);
            }
#pragma unroll
            for (int p = 0; p < 2; p++) {
                uint32_t off = (uint32_t)(((nw + p * 16 + lrow) * GP + kb + lc8) * 2);
                uint32_t b4h[4], b4l[4];
                ldsm4(b4h, uWh + off);
                ldsm4(b4l, uWl + off);
                uint32_t bhe[2] = {b4h[0], b4h[2]}, bho[2] = {b4h[1], b4h[3]};
                uint32_t ble[2] = {b4l[0], b4l[2]}, blq[2] = {b4l[1], b4l[3]};
#pragma unroll
                for (int mf = 0; mf < 2; mf++) {
                    mma16(c[mf][2 * p],     ah[mf], bhe);
                    mma16(c[mf][2 * p],     ah[mf], ble);
                    mma16(c[mf][2 * p],     al[mf], bhe);
                    mma16(c[mf][2 * p + 1], ah[mf], bho);
                    mma16(c[mf][2 * p + 1], ah[mf], blq);
                    mma16(c[mf][2 * p + 1], al[mf], bho);
                }
            }
        }

        if (cc + 1 < nc) store_stage(s ^ 1, ra, rb);
        __syncthreads();
    }

    // epilogue: pack split-bf16 and scatter
#pragma unroll
    for (int mf = 0; mf < 2; mf++) {
#pragma unroll
        for (int i = 0; i < 4; i++) {
            const int m = bm + mw + mf * 16 + g + ((i >> 1) << 3);
            const int b = m >> 11, sidx = m & 2047;
#pragma unroll
            for (int nf = 0; nf < 4; nf++) {
                const int n = bn + nw + nf * 8 + (t << 1) + (i & 1);
                const uint32_t pv = bpack(c[mf][nf][i]);
                if (MODE == 0) {
                    const int h = n / DQK, d = n % DQK;
                    g_q2[(((size_t)(b * HH + h)) * SS + sidx) * DQK + d] = pv;
                } else {
                    const int h = n >> 8, d = n & 255;
                    if (d < NOPE)
                        g_k2[(((size_t)(b * HH + h)) * SS + sidx) * DQK + d] = pv;
                    else
                        g_v2t[(((size_t)(b * HH + h)) * VD + (d - NOPE)) * SS + sidx] = pv;
                }
            }
        }
    }
}

// ---------------------------------------------------------------------------
// RoPE on packed arrays
// ---------------------------------------------------------------------------
__global__ void rope_kernel(const float* __restrict__ PE,
                            const float* __restrict__ cosb,
                            const float* __restrict__ sinb) {
    int tt = blockIdx.x * blockDim.x + threadIdx.x;
    if (tt >= BB * SS * 32) return;
    int i = tt & 31;
    int bs = tt >> 5;
    int b = bs / SS, s = bs % SS;

    float c  = cosb[(size_t)bs * ROPE + i];
    float sn = sinb[(size_t)bs * ROPE + i];

    float p1 = PE[(size_t)bs * ROPE + i];
    float p2 = PE[(size_t)bs * ROPE + i + 32];
    uint32_t k1 = bpack(p1 * c - p2 * sn);
    uint32_t k2 = bpack(p2 * c + p1 * sn);

#pragma unroll
    for (int h = 0; h < HH; h++) {
        size_t base = (((size_t)(b * HH + h)) * SS + s) * DQK + NOPE;
        float x1 = bunpack(g_q2[base + i]);
        float x2 = bunpack(g_q2[base + i + 32]);
        g_q2[base + i]      = bpack(x1 * c - x2 * sn);
        g_q2[base + i + 32] = bpack(x2 * c + x1 * sn);
        g_k2[base + i]      = k1;
        g_k2[base + i + 32] = k2;
    }
}

// ---------------------------------------------------------------------------
// Flash attention (causal): BQ=128, BK=64, 256 threads (8 warps x m16),
// register softmax + C->A fragment repack; fully-masked warp-tiles skipped.
// ---------------------------------------------------------------------------
#define QP2 200   // Q/K smem pitch (halfs)
#define VP2 72    // V pitch (halfs)
#define FL_SMEM_BYTES ((2*128*QP2 + 2*64*QP2 + 2*128*VP2) * 2)

extern __shared__ unsigned short fsm2[];

__global__ __launch_bounds__(256, 1) void flash_kernel(float* __restrict__ out) {
    const int qt = gridDim.x - 1 - blockIdx.x;   // heavy CTAs first
    const int h = blockIdx.y, b = blockIdx.z;
    const int tid = threadIdx.x;
    const int w = tid >> 5, lane = tid & 31;
    const int g = lane >> 2, t = lane & 3;
    const int lrow = lane & 15, lc8 = (lane >> 4) << 3;

    unsigned short* sQh = fsm2;
    unsigned short* sQl = sQh + 128 * QP2;
    unsigned short* sKh = sQl + 128 * QP2;
    unsigned short* sKl = sKh + 64 * QP2;
    unsigned short* sVh = sKl + 64 * QP2;
    unsigned short* sVl = sVh + 128 * VP2;

    const uint32_t uQh = smem_u32(sQh), uQl = smem_u32(sQl);
    const uint32_t uKh = smem_u32(sKh), uKl = smem_u32(sKl);
    const uint32_t uVh = smem_u32(sVh), uVl = smem_u32(sVl);

    const int wm = w * 16;          // this warp's q-row slab
    const int q0 = qt * 128;
    const size_t bh = (size_t)(b * HH + h);
    const size_t qbase = (bh * SS + q0) * DQK;

#pragma unroll
    for (int i = 0; i < 24; i++) {
        int idx = tid + i * 256;
        int r = idx / 48, ch = idx % 48;
        uint4 v = *(const uint4*)&g_q2[qbase + (size_t)r * DQK + ch * 4];
        uint32_t h0 = __byte_perm(v.x, v.y, PERM_HI), l0 = __byte_perm(v.x, v.y, PERM_LO);
        uint32_t h1 = __byte_perm(v.z, v.w, PERM_HI), l1 = __byte_perm(v.z, v.w, PERM_LO);
        int doff = r * QP2 + ch * 4;
        *(uint2*)&sQh[doff] = make_uint2(h0, h1);
        *(uint2*)&sQl[doff] = make_uint2(l0, l1);
    }

    const int r0g = q0 + wm + g;
    const int r1g = r0g + 8;

    float po[16][4] = {};
    float m0 = -1e30f, m1 = -1e30f, l0 = 0.f, l1 = 0.f;

    const int nkt = 2 * (qt + 1);
    for (int kt = 0; kt < nkt; kt++) {
        const int k0 = kt * 64;
        const size_t kbase = (bh * SS + k0) * DQK;

        __syncthreads();
#pragma unroll
        for (int i = 0; i < 12; i++) {
            int idx = tid + i * 256;
            int r = idx / 48, ch = idx % 48;
            uint4 v = *(const uint4*)&g_k2[kbase + (size_t)r * DQK + ch * 4];
            uint32_t h0 = __byte_perm(v.x, v.y, PERM_HI), lo0 = __byte_perm(v.x, v.y, PERM_LO);
            uint32_t h1 = __byte_perm(v.z, v.w, PERM_HI), lo1 = __byte_perm(v.z, v.w, PERM_LO);
            int doff = r * QP2 + ch * 4;
            *(uint2*)&sKh[doff] = make_uint2(h0, h1);
            *(uint2*)&sKl[doff] = make_uint2(lo0, lo1);
        }
#pragma unroll
        for (int i = 0; i < 8; i++) {
            int idx = tid + i * 256;
            int r = idx >> 4, ch = idx & 15;
            uint4 v = *(const uint4*)&g_v2t[(bh * VD + r) * SS + k0 + ch * 4];
            uint32_t h0 = __byte_perm(v.x, v.y, PERM_HI), lo0 = __byte_perm(v.x, v.y, PERM_LO);
            uint32_t h1 = __byte_perm(v.z, v.w, PERM_HI), lo1 = __byte_perm(v.z, v.w, PERM_LO);
            int doff = r * VP2 + ch * 4;
            *(uint2*)&sVh[doff] = make_uint2(h0, h1);
            *(uint2*)&sVl[doff] = make_uint2(lo0, lo1);
        }
        __syncthreads();

        // skip fully-masked warp-tiles (all cols > warp's max row)
        if (k0 > q0 + wm + 15) continue;

        // ---- scores ----
        float sc[8][4] = {};
#pragma unroll
        for (int kk = 0; kk < 12; kk++) {
            const int kb = kk << 4;
            uint32_t ah[4], al[4];
            uint32_t off = (uint32_t)(((wm + lrow) * QP2 + kb + lc8) * 2);
            ldsm4(ah, uQh + off);
            ldsm4(al, uQl + off);
#pragma unroll
            for (int p = 0; p < 4; p++) {
                uint32_t koff = (uint32_t)(((p * 16 + lrow) * QP2 + kb + lc8) * 2);
                uint32_t b4h[4], b4l[4];
                ldsm4(b4h, uKh + koff);
                ldsm4(b4l, uKl + koff);
                uint32_t bhe[2] = {b4h[0], b4h[2]}, bho[2] = {b4h[1], b4h[3]};
                uint32_t ble[2] = {b4l[0], b4l[2]}, blq[2] = {b4l[1], b4l[3]};
                mma16(sc[2 * p],     ah, bhe);
                mma16(sc[2 * p],     ah, ble);
                mma16(sc[2 * p],     al, bhe);
                mma16(sc[2 * p + 1], ah, bho);
                mma16(sc[2 * p + 1], ah, blq);
                mma16(sc[2 * p + 1], al, bho);
            }
        }

        // ---- mask + scale + register online softmax ----
        const bool needmask = (k0 + 63 > r0g);
        float mx0 = -1e30f, mx1 = -1e30f;
#pragma unroll
        for (int nf = 0; nf < 8; nf++) {
            const int c0 = k0 + nf * 8 + (t << 1);
            if (needmask) {
                sc[nf][0] = (c0     > r0g) ? -1e30f : sc[nf][0] * SCALE;
                sc[nf][1] = (c0 + 1 > r0g) ? -1e30f : sc[nf][1] * SCALE;
                sc[nf][2] = (c0     > r1g) ? -1e30f : sc[nf][2] * SCALE;
                sc[nf][3] = (c0 + 1 > r1g) ? -1e30f : sc[nf][3] * SCALE;
            } else {
                sc[nf][0] *= SCALE; sc[nf][1] *= SCALE;
                sc[nf][2] *= SCALE; sc[nf][3] *= SCALE;
            }
            mx0 = fmaxf(mx0, fmaxf(sc[nf][0], sc[nf][1]));
            mx1 = fmaxf(mx1, fmaxf(sc[nf][2], sc[nf][3]));
        }
        mx0 = fmaxf(mx0, __shfl_xor_sync(0xffffffffu, mx0, 1));
        mx0 = fmaxf(mx0, __shfl_xor_sync(0xffffffffu, mx0, 2));
        mx1 = fmaxf(mx1, __shfl_xor_sync(0xffffffffu, mx1, 1));
        mx1 = fmaxf(mx1, __shfl_xor_sync(0xffffffffu, mx1, 2));
        mx0 = fmaxf(mx0, m0);
        mx1 = fmaxf(mx1, m1);
        const float al0 = __expf(m0 - mx0);
        const float al1 = __expf(m1 - mx1);
        m0 = mx0; m1 = mx1;

        uint32_t pah[4][4], pal[4][4];
        float s0 = 0.f, s1 = 0.f;
#pragma unroll
        for (int j = 0; j < 4; j++) {
            float p00 = __expf(sc[2 * j][0] - mx0), p01 = __expf(sc[2 * j][1] - mx0);
            float p10 = __expf(sc[2 * j][2] - mx1), p11 = __expf(sc[2 * j][3] - mx1);
            float q00 = __expf(sc[2 * j + 1][0] - mx0), q01 = __expf(sc[2 * j + 1][1] - mx0);
            float q10 = __expf(sc[2 * j + 1][2] - mx1), q11 = __expf(sc[2 * j + 1][3] - mx1);
            s0 += p00 + p01 + q00 + q01;
            s1 += p10 + p11 + q10 + q11;
            pack_hl(p00, p01, pah[j][0], pal[j][0]);
            pack_hl(p10, p11, pah[j][1], pal[j][1]);
            pack_hl(q00, q01, pah[j][2], pal[j][2]);
            pack_hl(q10, q11, pah[j][3], pal[j][3]);
        }
        s0 += __shfl_xor_sync(0xffffffffu, s0, 1);
        s0 += __shfl_xor_sync(0xffffffffu, s0, 2);
        s1 += __shfl_xor_sync(0xffffffffu, s1, 1);
        s1 += __shfl_xor_sync(0xffffffffu, s1, 2);
        l0 = l0 * al0 + s0;
        l1 = l1 * al1 + s1;

        // ---- PV ----
#pragma unroll
        for (int nf = 0; nf < 16; nf++) {
            po[nf][0] *= al0; po[nf][1] *= al0;
            po[nf][2] *= al1; po[nf][3] *= al1;
        }
#pragma unroll
        for (int j = 0; j < 4; j++) {
            const int kb = j << 4;
#pragma unroll
            for (int p = 0; p < 8; p++) {
                uint32_t voff = (uint32_t)(((p * 16 + lrow) * VP2 + kb + lc8) * 2);
                uint32_t b4h[4], b4l[4];
                ldsm4(b4h, uVh + voff);
                ldsm4(b4l, uVl + voff);
                uint32_t bhe[2] = {b4h[0], b4h[2]}, bho[2] = {b4h[1], b4h[3]};
                uint32_t ble[2] = {b4l[0], b4l[2]}, blq[2] = {b4l[1], b4l[3]};
                mma16(po[2 * p],     pah[j], bhe);
                mma16(po[2 * p],     pah[j], ble);
                mma16(po[2 * p],     pal[j], bhe);
                mma16(po[2 * p + 1], pah[j], bho);
                mma16(po[2 * p + 1], pah[j], blq);
                mma16(po[2 * p + 1], pal[j], bho);
            }
        }
    }

    // epilogue
    {
        const float iv0 = 1.f / l0;
        const float iv1 = 1.f / l1;
        const size_t ob0 = (((size_t)b * SS + r0g) * HH + h) * VD;
        const size_t ob1 = (((size_t)b * SS + r1g) * HH + h) * VD;
#pragma unroll
        for (int nf = 0; nf < 16; nf++) {
            const int cl = nf * 8 + (t << 1);
            *(float2*)&out[ob0 + cl] = make_float2(po[nf][0] * iv0, po[nf][1] * iv0);
            *(float2*)&out[ob1 + cl] = make_float2(po[nf][2] * iv1, po[nf][3] * iv1);
        }
    }
}

// ---------------------------------------------------------------------------
extern "C" void kernel_launch(void* const* d_in, const int* in_sizes, int n_in,
                              void* d_out, int out_size) {
    const float* Q    = (const float*)d_in[0];
    const float* KV   = (const float*)d_in[1];
    const float* PE   = (const float*)d_in[2];
    const float* WUQ  = (const float*)d_in[3];
    const float* WUKV = (const float*)d_in[4];
    const float* cosb = (const float*)d_in[5];
    const float* sinb = (const float*)d_in[6];
    float* out = (float*)d_out;
    (void)in_sizes; (void)n_in; (void)out_size;

    cudaFuncSetAttribute(flash_kernel, cudaFuncAttributeMaxDynamicSharedMemorySize,
                         FL_SMEM_BYTES);
    cudaFuncSetAttribute(gemm_mma_kernel<0>, cudaFuncAttributeMaxDynamicSharedMemorySize,
                         GSMEM_TOTAL);
    cudaFuncSetAttribute(gemm_mma_kernel<1>, cudaFuncAttributeMaxDynamicSharedMemorySize,
                         GSMEM_TOTAL);

    // pre-split inputs + weights to packed split-bf16
    presplit_kernel<0><<<(MM * QR / 4 + 255) / 256, 256>>>(Q,    MM * QR / 4);
    presplit_kernel<1><<<(MM * KVR / 4 + 255) / 256, 256>>>(KV,   MM * KVR / 4);
    presplit_kernel<2><<<(NQ * QR / 4 + 255) / 256, 256>>>(WUQ,  NQ * QR / 4);
    presplit_kernel<3><<<(NKV * KVR / 4 + 255) / 256, 256>>>(WUKV, NKV * KVR / 4);

    dim3 g1(NQ / 128, MM / 128);   // (24, 32)
    gemm_mma_kernel<0><<<g1, 512, GSMEM_TOTAL>>>();

    dim3 g2(NKV / 128, MM / 128);  // (32, 32)
    gemm_mma_kernel<1><<<g2, 512, GSMEM_TOTAL>>>();

    int nrope = BB * SS * 32;
    rope_kernel<<<(nrope + 255) / 256, 256>>>(PE, cosb, sinb);

    dim3 gf(SS / 128, HH, BB);     // (16, 16, 2)
    flash_kernel<<<gf, 256, FL_SMEM_BYTES>>>(out);
}

// round 9
// speedup vs baseline: 8.4078x; 1.3486x over previous
#include <cuda_runtime.h>
#include <cuda_fp16.h>
#include <math.h>
#include <stdint.h>

#define BB 2
#define SS 2048
#define HH 16
#define NOPE 128
#define ROPE 64
#define VD 128
#define DQK 192           // NOPE + ROPE
#define QR 1536
#define KVR 512
#define NQ (HH*DQK)       // 3072
#define NKV (HH*(NOPE+VD))// 4096
#define MM (BB*SS)        // 4096
#define SCALE 0.07216878364870323f  // 1/sqrt(192)

// Packed split-fp16: each uint32 = (hi_fp16 | lo_fp16<<16), x = hi + lo
__device__ uint32_t g_q2[(size_t)BB*HH*SS*DQK];   // [b,h,s,192]
__device__ uint32_t g_k2[(size_t)BB*HH*SS*DQK];   // [b,h,s,192]
__device__ uint32_t g_v2t[(size_t)BB*HH*VD*SS];   // [b,h,d,s]  (transposed)
// pre-split inputs/weights
__device__ uint32_t g_qs[(size_t)MM*QR];
__device__ uint32_t g_kvs[(size_t)MM*KVR];
__device__ uint32_t g_wuqs[(size_t)NQ*QR];
__device__ uint32_t g_wukvs[(size_t)NKV*KVR];

// ---------------------------------------------------------------------------
// helpers
// ---------------------------------------------------------------------------
__device__ __forceinline__ uint32_t smem_u32(const void* p) {
    uint32_t a;
    asm("{ .reg .u64 t; cvta.to.shared.u64 t, %1; cvt.u32.u64 %0, t; }" : "=r"(a) : "l"(p));
    return a;
}
__device__ __forceinline__ void ldsm4(uint32_t* r, uint32_t addr) {
    asm volatile("ldmatrix.sync.aligned.m8n8.x4.shared.b16 {%0,%1,%2,%3}, [%4];"
                 : "=r"(r[0]), "=r"(r[1]), "=r"(r[2]), "=r"(r[3]) : "r"(addr));
}
__device__ __forceinline__ void mma16(float* c, const uint32_t* a, const uint32_t* b) {
    asm volatile("mma.sync.aligned.m16n8k16.row.col.f32.f16.f16.f32 "
                 "{%0,%1,%2,%3}, {%4,%5,%6,%7}, {%8,%9}, {%0,%1,%2,%3};"
                 : "+f"(c[0]), "+f"(c[1]), "+f"(c[2]), "+f"(c[3])
                 : "r"(a[0]), "r"(a[1]), "r"(a[2]), "r"(a[3]), "r"(b[0]), "r"(b[1]));
}
__device__ __forceinline__ uint32_t hpack(float x) {
    __half h = __float2half_rn(x);
    float r = x - __half2float(h);
    __half l = __float2half_rn(r);
    return (uint32_t)__half_as_ushort(h) | ((uint32_t)__half_as_ushort(l) << 16);
}
__device__ __forceinline__ float hunpack(uint32_t u) {
    return __half2float(__ushort_as_half((unsigned short)(u & 0xffffu)))
         + __half2float(__ushort_as_half((unsigned short)(u >> 16)));
}
__device__ __forceinline__ void pack_hl(float x, float y, uint32_t& hi, uint32_t& lo) {
    __half2 h = __floats2half2_rn(x, y);
    float rx = x - __half2float(h.x);
    float ry = y - __half2float(h.y);
    __half2 l = __floats2half2_rn(rx, ry);
    hi = *(uint32_t*)&h;
    lo = *(uint32_t*)&l;
}
#define PERM_HI 0x5410
#define PERM_LO 0x7632

// ---------------------------------------------------------------------------
// pre-split: float -> packed split-fp16.  WHICH selects destination.
// ---------------------------------------------------------------------------
template<int WHICH>
__global__ void presplit_kernel(const float* __restrict__ src, int n4) {
    int i = blockIdx.x * blockDim.x + threadIdx.x;
    if (i >= n4) return;
    uint32_t* dst = (WHICH == 0) ? g_qs : (WHICH == 1) ? g_kvs
                  : (WHICH == 2) ? g_wuqs : g_wukvs;
    float4 v = ((const float4*)src)[i];
    uint4 o;
    o.x = hpack(v.x); o.y = hpack(v.y); o.z = hpack(v.z); o.w = hpack(v.w);
    ((uint4*)dst)[i] = o;
}

// ---------------------------------------------------------------------------
// GEMM (split-fp16, 2-term): C[m,n] = sum_k A[m,k]*W[n,k]
// CTA 128x128, 512 threads (16 warps, 4m x 4n), K-chunk 32, 2-stage smem.
// A side hi+lo, W side hi only.
// ---------------------------------------------------------------------------
#define GP 40                 // smem row pitch (halfs)
#define GTILE (128*GP)        // halfs per tile (5120) = 10240 B
#define GSTAGE (3*GTILE*2)    // bytes per stage (Ah, Al, Wh) = 30720
#define GSMEM_TOTAL (2*GSTAGE)

extern __shared__ char gsm[];

template<int MODE>
__global__ __launch_bounds__(512) void gemm_mma_kernel() {
    const uint32_t* A = (MODE == 0) ? g_qs : g_kvs;
    const uint32_t* W = (MODE == 0) ? g_wuqs : g_wukvs;
    const int K = (MODE == 0) ? QR : KVR;

    const int tid = threadIdx.x;
    const int w = tid >> 5, lane = tid & 31;
    const int g = lane >> 2, t = lane & 3;
    const int lrow = lane & 15, lc8 = (lane >> 4) << 3;
    const int bm = blockIdx.y * 128, bn = blockIdx.x * 128;
    const int mw = (w >> 2) * 32, nw = (w & 3) * 32;
    const uint32_t uS = smem_u32(gsm);

    int rr[2], rf[2];
#pragma unroll
    for (int i = 0; i < 2; i++) {
        int idx = tid + i * 512;
        rr[i] = idx >> 3; rf[i] = (idx & 7) << 2;
    }

    auto store_stage = [&](int s, const uint4* va, const uint4* vb) {
        unsigned short* pAh = (unsigned short*)(gsm + s * GSTAGE);
        unsigned short* pAl = pAh + GTILE;
        unsigned short* pWh = pAl + GTILE;
#pragma unroll
        for (int i = 0; i < 2; i++) {
            const int off = rr[i] * GP + rf[i];
            uint32_t h0 = __byte_perm(va[i].x, va[i].y, PERM_HI);
            uint32_t l0 = __byte_perm(va[i].x, va[i].y, PERM_LO);
            uint32_t h1 = __byte_perm(va[i].z, va[i].w, PERM_HI);
            uint32_t l1 = __byte_perm(va[i].z, va[i].w, PERM_LO);
            *(uint2*)&pAh[off] = make_uint2(h0, h1);
            *(uint2*)&pAl[off] = make_uint2(l0, l1);
            h0 = __byte_perm(vb[i].x, vb[i].y, PERM_HI);
            h1 = __byte_perm(vb[i].z, vb[i].w, PERM_HI);
            *(uint2*)&pWh[off] = make_uint2(h0, h1);
        }
    };

    float c[2][4][4] = {};
    uint4 ra[2], rb[2];
#pragma unroll
    for (int i = 0; i < 2; i++) {
        ra[i] = *(const uint4*)&A[(size_t)(bm + rr[i]) * K + rf[i]];
        rb[i] = *(const uint4*)&W[(size_t)(bn + rr[i]) * K + rf[i]];
    }
    store_stage(0, ra, rb);
    __syncthreads();

    const int nc = K >> 5;
    for (int cc = 0; cc < nc; cc++) {
        const int s = cc & 1;
        if (cc + 1 < nc) {
            const int k0 = (cc + 1) << 5;
#pragma unroll
            for (int i = 0; i < 2; i++) {
                ra[i] = *(const uint4*)&A[(size_t)(bm + rr[i]) * K + k0 + rf[i]];
                rb[i] = *(const uint4*)&W[(size_t)(bn + rr[i]) * K + k0 + rf[i]];
            }
        }

        const uint32_t uAh = uS + s * GSTAGE;
        const uint32_t uAl = uAh + GTILE * 2;
        const uint32_t uWh = uAl + GTILE * 2;
#pragma unroll
        for (int kk = 0; kk < 2; kk++) {
            const int kb = kk << 4;
            uint32_t ah[2][4], al[2][4];
#pragma unroll
            for (int mf = 0; mf < 2; mf++) {
                uint32_t off = (uint32_t)(((mw + mf * 16 + lrow) * GP + kb + lc8) * 2);
                ldsm4(ah[mf], uAh + off);
                ldsm4(al[mf], uAl + off);
            }
#pragma unroll
            for (int p = 0; p < 2; p++) {
                uint32_t off = (uint32_t)(((nw + p * 16 + lrow) * GP + kb + lc8) * 2);
                uint32_t b4h[4];
                ldsm4(b4h, uWh + off);
                uint32_t bhe[2] = {b4h[0], b4h[2]}, bho[2] = {b4h[1], b4h[3]};
#pragma unroll
                for (int mf = 0; mf < 2; mf++) {
                    mma16(c[mf][2 * p],     ah[mf], bhe);
                    mma16(c[mf][2 * p],     al[mf], bhe);
                    mma16(c[mf][2 * p + 1], ah[mf], bho);
                    mma16(c[mf][2 * p + 1], al[mf], bho);
                }
            }
        }

        if (cc + 1 < nc) store_stage(s ^ 1, ra, rb);
        __syncthreads();
    }

    // epilogue: pack split-fp16 and scatter
#pragma unroll
    for (int mf = 0; mf < 2; mf++) {
#pragma unroll
        for (int i = 0; i < 4; i++) {
            const int m = bm + mw + mf * 16 + g + ((i >> 1) << 3);
            const int b = m >> 11, sidx = m & 2047;
#pragma unroll
            for (int nf = 0; nf < 4; nf++) {
                const int n = bn + nw + nf * 8 + (t << 1) + (i & 1);
                const uint32_t pv = hpack(c[mf][nf][i]);
                if (MODE == 0) {
                    const int h = n / DQK, d = n % DQK;
                    g_q2[(((size_t)(b * HH + h)) * SS + sidx) * DQK + d] = pv;
                } else {
                    const int h = n >> 8, d = n & 255;
                    if (d < NOPE)
                        g_k2[(((size_t)(b * HH + h)) * SS + sidx) * DQK + d] = pv;
                    else
                        g_v2t[(((size_t)(b * HH + h)) * VD + (d - NOPE)) * SS + sidx] = pv;
                }
            }
        }
    }
}

// ---------------------------------------------------------------------------
// RoPE on packed arrays
// ---------------------------------------------------------------------------
__global__ void rope_kernel(const float* __restrict__ PE,
                            const float* __restrict__ cosb,
                            const float* __restrict__ sinb) {
    int tt = blockIdx.x * blockDim.x + threadIdx.x;
    if (tt >= BB * SS * 32) return;
    int i = tt & 31;
    int bs = tt >> 5;
    int b = bs / SS, s = bs % SS;

    float c  = cosb[(size_t)bs * ROPE + i];
    float sn = sinb[(size_t)bs * ROPE + i];

    float p1 = PE[(size_t)bs * ROPE + i];
    float p2 = PE[(size_t)bs * ROPE + i + 32];
    uint32_t k1 = hpack(p1 * c - p2 * sn);
    uint32_t k2 = hpack(p2 * c + p1 * sn);

#pragma unroll
    for (int h = 0; h < HH; h++) {
        size_t base = (((size_t)(b * HH + h)) * SS + s) * DQK + NOPE;
        float x1 = hunpack(g_q2[base + i]);
        float x2 = hunpack(g_q2[base + i + 32]);
        g_q2[base + i]      = hpack(x1 * c - x2 * sn);
        g_q2[base + i + 32] = hpack(x2 * c + x1 * sn);
        g_k2[base + i]      = k1;
        g_k2[base + i + 32] = k2;
    }
}

// ---------------------------------------------------------------------------
// Flash attention (causal): BQ=128, BK=64, 256 threads (8 warps x m16).
// fp16 2-term: Q/P carry hi+lo; K/V hi only. Register softmax.
// ---------------------------------------------------------------------------
#define QP2 200   // Q/K smem pitch (halfs)
#define VP2 72    // V pitch (halfs)
#define FL_SMEM_BYTES ((2*128*QP2 + 64*QP2 + 128*VP2) * 2)

extern __shared__ unsigned short fsm2[];

__global__ __launch_bounds__(256, 1) void flash_kernel(float* __restrict__ out) {
    const int qt = gridDim.x - 1 - blockIdx.x;   // heavy CTAs first
    const int h = blockIdx.y, b = blockIdx.z;
    const int tid = threadIdx.x;
    const int w = tid >> 5, lane = tid & 31;
    const int g = lane >> 2, t = lane & 3;
    const int lrow = lane & 15, lc8 = (lane >> 4) << 3;

    unsigned short* sQh = fsm2;
    unsigned short* sQl = sQh + 128 * QP2;
    unsigned short* sKh = sQl + 128 * QP2;
    unsigned short* sVh = sKh + 64 * QP2;

    const uint32_t uQh = smem_u32(sQh), uQl = smem_u32(sQl);
    const uint32_t uKh = smem_u32(sKh);
    const uint32_t uVh = smem_u32(sVh);

    const int wm = w * 16;
    const int q0 = qt * 128;
    const size_t bh = (size_t)(b * HH + h);
    const size_t qbase = (bh * SS + q0) * DQK;

#pragma unroll
    for (int i = 0; i < 24; i++) {
        int idx = tid + i * 256;
        int r = idx / 48, ch = idx % 48;
        uint4 v = *(const uint4*)&g_q2[qbase + (size_t)r * DQK + ch * 4];
        uint32_t h0 = __byte_perm(v.x, v.y, PERM_HI), l0 = __byte_perm(v.x, v.y, PERM_LO);
        uint32_t h1 = __byte_perm(v.z, v.w, PERM_HI), l1 = __byte_perm(v.z, v.w, PERM_LO);
        int doff = r * QP2 + ch * 4;
        *(uint2*)&sQh[doff] = make_uint2(h0, h1);
        *(uint2*)&sQl[doff] = make_uint2(l0, l1);
    }

    const int r0g = q0 + wm + g;
    const int r1g = r0g + 8;

    float po[16][4] = {};
    float m0 = -1e30f, m1 = -1e30f, l0 = 0.f, l1 = 0.f;

    const int nkt = 2 * (qt + 1);
    for (int kt = 0; kt < nkt; kt++) {
        const int k0 = kt * 64;
        const size_t kbase = (bh * SS + k0) * DQK;

        __syncthreads();
#pragma unroll
        for (int i = 0; i < 12; i++) {
            int idx = tid + i * 256;
            int r = idx / 48, ch = idx % 48;
            uint4 v = *(const uint4*)&g_k2[kbase + (size_t)r * DQK + ch * 4];
            uint32_t h0 = __byte_perm(v.x, v.y, PERM_HI);
            uint32_t h1 = __byte_perm(v.z, v.w, PERM_HI);
            *(uint2*)&sKh[r * QP2 + ch * 4] = make_uint2(h0, h1);
        }
#pragma unroll
        for (int i = 0; i < 8; i++) {
            int idx = tid + i * 256;
            int r = idx >> 4, ch = idx & 15;
            uint4 v = *(const uint4*)&g_v2t[(bh * VD + r) * SS + k0 + ch * 4];
            uint32_t h0 = __byte_perm(v.x, v.y, PERM_HI);
            uint32_t h1 = __byte_perm(v.z, v.w, PERM_HI);
            *(uint2*)&sVh[r * VP2 + ch * 4] = make_uint2(h0, h1);
        }
        __syncthreads();

        // skip fully-masked warp-tiles
        if (k0 > q0 + wm + 15) continue;

        // ---- scores ----
        float sc[8][4] = {};
#pragma unroll
        for (int kk = 0; kk < 12; kk++) {
            const int kb = kk << 4;
            uint32_t ah[4], al[4];
            uint32_t off = (uint32_t)(((wm + lrow) * QP2 + kb + lc8) * 2);
            ldsm4(ah, uQh + off);
            ldsm4(al, uQl + off);
#pragma unroll
            for (int p = 0; p < 4; p++) {
                uint32_t koff = (uint32_t)(((p * 16 + lrow) * QP2 + kb + lc8) * 2);
                uint32_t b4h[4];
                ldsm4(b4h, uKh + koff);
                uint32_t bhe[2] = {b4h[0], b4h[2]}, bho[2] = {b4h[1], b4h[3]};
                mma16(sc[2 * p],     ah, bhe);
                mma16(sc[2 * p],     al, bhe);
                mma16(sc[2 * p + 1], ah, bho);
                mma16(sc[2 * p + 1], al, bho);
            }
        }

        // ---- mask + scale + register online softmax ----
        const bool needmask = (k0 + 63 > r0g);
        float mx0 = -1e30f, mx1 = -1e30f;
#pragma unroll
        for (int nf = 0; nf < 8; nf++) {
            const int c0 = k0 + nf * 8 + (t << 1);
            if (needmask) {
                sc[nf][0] = (c0     > r0g) ? -1e30f : sc[nf][0] * SCALE;
                sc[nf][1] = (c0 + 1 > r0g) ? -1e30f : sc[nf][1] * SCALE;
                sc[nf][2] = (c0     > r1g) ? -1e30f : sc[nf][2] * SCALE;
                sc[nf][3] = (c0 + 1 > r1g) ? -1e30f : sc[nf][3] * SCALE;
            } else {
                sc[nf][0] *= SCALE; sc[nf][1] *= SCALE;
                sc[nf][2] *= SCALE; sc[nf][3] *= SCALE;
            }
            mx0 = fmaxf(mx0, fmaxf(sc[nf][0], sc[nf][1]));
            mx1 = fmaxf(mx1, fmaxf(sc[nf][2], sc[nf][3]));
        }
        mx0 = fmaxf(mx0, __shfl_xor_sync(0xffffffffu, mx0, 1));
        mx0 = fmaxf(mx0, __shfl_xor_sync(0xffffffffu, mx0, 2));
        mx1 = fmaxf(mx1, __shfl_xor_sync(0xffffffffu, mx1, 1));
        mx1 = fmaxf(mx1, __shfl_xor_sync(0xffffffffu, mx1, 2));
        mx0 = fmaxf(mx0, m0);
        mx1 = fmaxf(mx1, m1);
        const float al0 = __expf(m0 - mx0);
        const float al1 = __expf(m1 - mx1);
        m0 = mx0; m1 = mx1;

        uint32_t pah[4][4], pal[4][4];
        float s0 = 0.f, s1 = 0.f;
#pragma unroll
        for (int j = 0; j < 4; j++) {
            float p00 = __expf(sc[2 * j][0] - mx0), p01 = __expf(sc[2 * j][1] - mx0);
            float p10 = __expf(sc[2 * j][2] - mx1), p11 = __expf(sc[2 * j][3] - mx1);
            float q00 = __expf(sc[2 * j + 1][0] - mx0), q01 = __expf(sc[2 * j + 1][1] - mx0);
            float q10 = __expf(sc[2 * j + 1][2] - mx1), q11 = __expf(sc[2 * j + 1][3] - mx1);
            s0 += p00 + p01 + q00 + q01;
            s1 += p10 + p11 + q10 + q11;
            pack_hl(p00, p01, pah[j][0], pal[j][0]);
            pack_hl(p10, p11, pah[j][1], pal[j][1]);
            pack_hl(q00, q01, pah[j][2], pal[j][2]);
            pack_hl(q10, q11, pah[j][3], pal[j][3]);
        }
        s0 += __shfl_xor_sync(0xffffffffu, s0, 1);
        s0 += __shfl_xor_sync(0xffffffffu, s0, 2);
        s1 += __shfl_xor_sync(0xffffffffu, s1, 1);
        s1 += __shfl_xor_sync(0xffffffffu, s1, 2);
        l0 = l0 * al0 + s0;
        l1 = l1 * al1 + s1;

        // ---- PV ----
#pragma unroll
        for (int nf = 0; nf < 16; nf++) {
            po[nf][0] *= al0; po[nf][1] *= al0;
            po[nf][2] *= al1; po[nf][3] *= al1;
        }
#pragma unroll
        for (int j = 0; j < 4; j++) {
            const int kb = j << 4;
#pragma unroll
            for (int p = 0; p < 8; p++) {
                uint32_t voff = (uint32_t)(((p * 16 + lrow) * VP2 + kb + lc8) * 2);
                uint32_t b4h[4];
                ldsm4(b4h, uVh + voff);
                uint32_t bhe[2] = {b4h[0], b4h[2]}, bho[2] = {b4h[1], b4h[3]};
                mma16(po[2 * p],     pah[j], bhe);
                mma16(po[2 * p],     pal[j], bhe);
                mma16(po[2 * p + 1], pah[j], bho);
                mma16(po[2 * p + 1], pal[j], bho);
            }
        }
    }

    // epilogue
    {
        const float iv0 = 1.f / l0;
        const float iv1 = 1.f / l1;
        const size_t ob0 = (((size_t)b * SS + r0g) * HH + h) * VD;
        const size_t ob1 = (((size_t)b * SS + r1g) * HH + h) * VD;
#pragma unroll
        for (int nf = 0; nf < 16; nf++) {
            const int cl = nf * 8 + (t << 1);
            *(float2*)&out[ob0 + cl] = make_float2(po[nf][0] * iv0, po[nf][1] * iv0);
            *(float2*)&out[ob1 + cl] = make_float2(po[nf][2] * iv1, po[nf][3] * iv1);
        }
    }
}

// ---------------------------------------------------------------------------
extern "C" void kernel_launch(void* const* d_in, const int* in_sizes, int n_in,
                              void* d_out, int out_size) {
    const float* Q    = (const float*)d_in[0];
    const float* KV   = (const float*)d_in[1];
    const float* PE   = (const float*)d_in[2];
    const float* WUQ  = (const float*)d_in[3];
    const float* WUKV = (const float*)d_in[4];
    const float* cosb = (const float*)d_in[5];
    const float* sinb = (const float*)d_in[6];
    float* out = (float*)d_out;
    (void)in_sizes; (void)n_in; (void)out_size;

    cudaFuncSetAttribute(flash_kernel, cudaFuncAttributeMaxDynamicSharedMemorySize,
                         FL_SMEM_BYTES);
    cudaFuncSetAttribute(gemm_mma_kernel<0>, cudaFuncAttributeMaxDynamicSharedMemorySize,
                         GSMEM_TOTAL);
    cudaFuncSetAttribute(gemm_mma_kernel<1>, cudaFuncAttributeMaxDynamicSharedMemorySize,
                         GSMEM_TOTAL);

    presplit_kernel<0><<<(MM * QR / 4 + 255) / 256, 256>>>(Q,    MM * QR / 4);
    presplit_kernel<1><<<(MM * KVR / 4 + 255) / 256, 256>>>(KV,   MM * KVR / 4);
    presplit_kernel<2><<<(NQ * QR / 4 + 255) / 256, 256>>>(WUQ,  NQ * QR / 4);
    presplit_kernel<3><<<(NKV * KVR / 4 + 255) / 256, 256>>>(WUKV, NKV * KVR / 4);

    dim3 g1(NQ / 128, MM / 128);   // (24, 32)
    gemm_mma_kernel<0><<<g1, 512, GSMEM_TOTAL>>>();

    dim3 g2(NKV / 128, MM / 128);  // (32, 32)
    gemm_mma_kernel<1><<<g2, 512, GSMEM_TOTAL>>>();

    int nrope = BB * SS * 32;
    rope_kernel<<<(nrope + 255) / 256, 256>>>(PE, cosb, sinb);

    dim3 gf(SS / 128, HH, BB);     // (16, 16, 2)
    flash_kernel<<<gf, 256, FL_SMEM_BYTES>>>(out);
}